// round 4
// baseline (speedup 1.0000x reference)
#include <cuda_runtime.h>
#include <math.h>

// Problem constants
#define Bn 4
#define Tn 2048
#define Dn 1024
#define Hn 16
#define Sn 64
#define NC 32
#define BT (Bn*Tn)   // 8192 rows

// ---------------- scratch ----------------
__device__ float g_xqf[4][BT*Dn];
__device__ float g_rkvg[4][BT*Dn];
__device__ float g_wq[5][Dn*Dn];
__device__ float g_wscale[5];
__device__ float g_y[BT*Dn];
__device__ float g_zq[BT*Dn];
__device__ float g_local[Bn*Hn*NC*Sn*Sn];
__device__ float g_init [Bn*Hn*NC*Sn*Sn];
__device__ float g_wpow[65*1024];   // wpow[n][h*64+s] = expf(n * log_w), ref-faithful fp32
__device__ float g_ue[Hn*Sn];

// ---------------- helpers ----------------
__device__ __forceinline__ double blockReduceSumD(double v, double* red) {
    int tid = threadIdx.x;
    red[tid] = v; __syncthreads();
    #pragma unroll
    for (int s = 128; s > 0; s >>= 1) {
        if (tid < s) red[tid] += red[tid + s];
        __syncthreads();
    }
    double r = red[0];
    __syncthreads();
    return r;
}

// ---------------- precompute: log_w powers table + u_exp ----------------
__global__ void k_params(const float* __restrict__ log_decay, const float* __restrict__ u) {
    int i = threadIdx.x;                  // 1024 = H*S
    float eld = expf(log_decay[i]);       // fp32, mimic jnp.exp
    float wf  = expf(-eld);               // w
    float lw  = logf(fmaxf(wf, 1e-38f));  // log_w = log(clip(w,1e-38))
    for (int n = 0; n <= 64; n++)
        g_wpow[n * 1024 + i] = expf(__fmul_rn((float)n, lw));
    g_ue[i] = expf(u[i]);
}

// ---------------- weight quantization (fp64-exact scale) ----------------
__global__ void k_wscale(const float* __restrict__ w) {   // grid 5, block 256
    __shared__ double red[256];
    const float* p = w + (size_t)blockIdx.x * Dn * Dn;
    double s = 0.0;
    for (int i = threadIdx.x; i < Dn * Dn; i += 256) s += (double)fabsf(p[i]);
    double tot = blockReduceSumD(s, red);
    if (threadIdx.x == 0)
        g_wscale[blockIdx.x] = fmaxf((float)(tot / (double)(Dn * Dn)), 1e-8f);
}

__global__ void k_wquant(const float* __restrict__ w) {   // grid 20480, block 256
    int i = blockIdx.x * 256 + threadIdx.x;
    int m = i / (Dn * Dn);
    float s  = g_wscale[m];
    float vn = __fdiv_rn(w[i], s);
    vn = fminf(fmaxf(vn, -1.f), 1.f);
    ((float*)g_wq)[i] = __fmul_rn(rintf(vn), s);
}

// ---------------- token shift + LN + act quant ----------------
__global__ void k_prep(const float* __restrict__ x,
                       const float* __restrict__ mu_r, const float* __restrict__ mu_k,
                       const float* __restrict__ mu_v, const float* __restrict__ mu_g,
                       const float* __restrict__ ln_g, const float* __restrict__ ln_b) {
    int row = blockIdx.x;           // b*T + t
    int t   = row % Tn;
    int tid = threadIdx.x;
    __shared__ float sx[Dn], sdx[Dn];
    __shared__ double red[256];
    const float* mus[4] = {mu_r, mu_k, mu_v, mu_g};

    #pragma unroll
    for (int i = 0; i < 4; i++) {
        int d = tid + i * 256;
        float xv = x[(size_t)row * Dn + d];
        float xp = (t > 0) ? x[(size_t)(row - 1) * Dn + d] : 0.f;
        sx[d]  = xv;
        sdx[d] = __fsub_rn(xp, xv);
    }
    __syncthreads();

    for (int v = 0; v < 4; v++) {
        const float* mu = mus[v];
        float inp[4];
        double s = 0.0;
        #pragma unroll
        for (int i = 0; i < 4; i++) {
            int d = tid + i * 256;
            inp[i] = __fadd_rn(sx[d], __fmul_rn(sdx[d], mu[d]));  // x + xx*mu, no fma
            s += (double)inp[i];
        }
        float mean = (float)(blockReduceSumD(s, red) * (1.0 / Dn));
        double s2 = 0.0;
        float dev[4];
        #pragma unroll
        for (int i = 0; i < 4; i++) {
            dev[i] = __fsub_rn(inp[i], mean);
            s2 += (double)__fmul_rn(dev[i], dev[i]);
        }
        float var  = (float)(blockReduceSumD(s2, red) * (1.0 / Dn));
        float rstd = (float)(1.0 / sqrt((double)__fadd_rn(var, 1e-5f)));
        float yv[4];
        double sa = 0.0;
        #pragma unroll
        for (int i = 0; i < 4; i++) {
            int d = tid + i * 256;
            // ((x-m)*rstd)*g + b, left-assoc, no fma
            float t1 = __fmul_rn(dev[i], rstd);
            float t2 = __fmul_rn(t1, ln_g[v * Dn + d]);
            yv[i] = __fadd_rn(t2, ln_b[v * Dn + d]);
            sa += (double)fabsf(yv[i]);
        }
        float meanabs = (float)(blockReduceSumD(sa, red) * (1.0 / Dn));
        float clipv = __fmul_rn(fmaxf(meanabs, 1e-8f), 2.5f);
        float scale = __fdiv_rn(clipv, 127.f);
        #pragma unroll
        for (int i = 0; i < 4; i++) {
            int d = tid + i * 256;
            float xs = __fdiv_rn(yv[i], scale);
            float xc = fminf(fmaxf(xs, -127.f), 127.f);
            g_xqf[v][(size_t)row * Dn + d] = __fmul_rn(rintf(xc), scale);
        }
    }
}

// ---------------- exact fp32 SIMT GEMM: C = A @ W^T ----------------
__global__ void __launch_bounds__(256, 2)
k_gemm(const float* __restrict__ A, const float* __restrict__ W, float* __restrict__ Cm) {
    const int K = Dn, N = Dn;
    __shared__ float As[8][128];
    __shared__ float Bs[8][128];
    int tid = threadIdx.x;
    int m0 = blockIdx.y * 128, n0 = blockIdx.x * 128;
    int lr = tid >> 1;
    int lc = (tid & 1) * 4;
    const float* Ap = A + (size_t)(m0 + lr) * K + lc;
    const float* Wp = W + (size_t)(n0 + lr) * K + lc;
    int trow = (tid >> 4) << 3;
    int tcol = (tid & 15) << 3;

    float acc[8][8];
    #pragma unroll
    for (int i = 0; i < 8; i++)
        #pragma unroll
        for (int j = 0; j < 8; j++) acc[i][j] = 0.f;

    for (int k0 = 0; k0 < K; k0 += 8) {
        float4 av = *(const float4*)(Ap + k0);
        float4 wv = *(const float4*)(Wp + k0);
        As[lc + 0][lr] = av.x; As[lc + 1][lr] = av.y; As[lc + 2][lr] = av.z; As[lc + 3][lr] = av.w;
        Bs[lc + 0][lr] = wv.x; Bs[lc + 1][lr] = wv.y; Bs[lc + 2][lr] = wv.z; Bs[lc + 3][lr] = wv.w;
        __syncthreads();
        #pragma unroll
        for (int kk = 0; kk < 8; kk++) {
            float4 a0 = *(const float4*)&As[kk][trow];
            float4 a1 = *(const float4*)&As[kk][trow + 4];
            float4 b0 = *(const float4*)&Bs[kk][tcol];
            float4 b1 = *(const float4*)&Bs[kk][tcol + 4];
            float ar[8] = {a0.x, a0.y, a0.z, a0.w, a1.x, a1.y, a1.z, a1.w};
            float br[8] = {b0.x, b0.y, b0.z, b0.w, b1.x, b1.y, b1.z, b1.w};
            #pragma unroll
            for (int i = 0; i < 8; i++)
                #pragma unroll
                for (int j = 0; j < 8; j++)
                    acc[i][j] = fmaf(ar[i], br[j], acc[i][j]);
        }
        __syncthreads();
    }
    #pragma unroll
    for (int i = 0; i < 8; i++) {
        float* cp = Cm + (size_t)(m0 + trow + i) * N + n0 + tcol;
        float4 c0 = {acc[i][0], acc[i][1], acc[i][2], acc[i][3]};
        float4 c1 = {acc[i][4], acc[i][5], acc[i][6], acc[i][7]};
        *(float4*)cp       = c0;
        *(float4*)(cp + 4) = c1;
    }
}

// ---------------- WKV phase 1: local[s,o] = sum_t wpow[63-t][s]*k[t,s]*v[t,o] ----------------
__global__ void k_wkv_local() {
    int o = threadIdx.x;            // 64
    int idx = blockIdx.x;           // 2048
    int c = idx & 31, h = (idx >> 5) & 15, b = idx >> 9;
    const float* kbuf = g_rkvg[1];
    const float* vbuf = g_rkvg[2];
    __shared__ float kk[64], drow[64];
    float ls[64];
    #pragma unroll
    for (int s = 0; s < 64; s++) ls[s] = 0.f;
    size_t rowbase = (size_t)(b * Tn + c * 64) * Dn + h * 64;
    for (int t = 0; t < 64; t++) {
        __syncthreads();
        kk[o]   = kbuf[rowbase + (size_t)t * Dn + o];
        drow[o] = g_wpow[(63 - t) * 1024 + h * 64 + o];
        __syncthreads();
        float vo = vbuf[rowbase + (size_t)t * Dn + o];
        #pragma unroll
        for (int s = 0; s < 64; s++)
            ls[s] = fmaf(drow[s], __fmul_rn(kk[s], vo), ls[s]);  // decay*(k*v)
    }
    float* lp = g_local + (size_t)idx * 4096;
    #pragma unroll
    for (int s = 0; s < 64; s++) lp[s * 64 + o] = ls[s];
}

// ---------------- WKV phase 2: scan over chunks ----------------
__global__ void k_wkv_scan() {      // grid 64, block 256
    int bh = blockIdx.x;
    int h  = bh & 15;
    int tid = threadIdx.x;
    float cur[16], wc[16];
    #pragma unroll
    for (int j = 0; j < 16; j++) {
        cur[j] = 0.f;
        int e = tid + j * 256;
        wc[j] = g_wpow[64 * 1024 + h * 64 + (e >> 6)];
    }
    for (int c = 0; c < NC; c++) {
        size_t base = ((size_t)bh * NC + c) * 4096;
        #pragma unroll
        for (int j = 0; j < 16; j++) {
            int e = tid + j * 256;
            g_init[base + e] = cur[j];
            cur[j] = __fadd_rn(__fmul_rn(wc[j], cur[j]), g_local[base + e]);
        }
    }
}

// ---------------- WKV phase 3: outputs ----------------
// y_t = r . ( Q_t + wpow[t+1] (.) S0 + u_exp (.) kv_t )
__global__ void k_wkv_out() {
    int o = threadIdx.x;            // 64
    int idx = blockIdx.x;           // 2048
    int c = idx & 31, h = (idx >> 5) & 15, b = idx >> 9;
    __shared__ float kk[64], rr[64], ww[64], ue[64], crow[64];
    ww[o] = g_wpow[1024 + h * 64 + o];   // w = wpow[1]
    ue[o] = g_ue[h * 64 + o];
    size_t rowbase = (size_t)(b * Tn + c * 64) * Dn + h * 64;

    // Pass A: y_t = r . (wpow[t+1] * S0)
    float A0[64];
    const float* ip = g_init + (size_t)idx * 4096;
    #pragma unroll
    for (int s = 0; s < 64; s++) A0[s] = ip[s * 64 + o];
    for (int t = 0; t < 64; t++) {
        __syncthreads();
        rr[o]   = g_rkvg[0][rowbase + (size_t)t * Dn + o];
        crow[o] = g_wpow[(t + 1) * 1024 + h * 64 + o];
        __syncthreads();
        float y = 0.f;
        #pragma unroll
        for (int s = 0; s < 64; s++)
            y = fmaf(rr[s], __fmul_rn(crow[s], A0[s]), y);
        g_y[rowbase + (size_t)t * Dn + o] = y;
    }

    // Pass B: backward Q recurrence + bonus
    float Q[64];
    #pragma unroll
    for (int s = 0; s < 64; s++) Q[s] = 0.f;
    for (int t = 63; t >= 0; t--) {
        __syncthreads();
        kk[o] = g_rkvg[1][rowbase + (size_t)t * Dn + o];
        rr[o] = g_rkvg[0][rowbase + (size_t)t * Dn + o];
        __syncthreads();
        float vo = g_rkvg[2][rowbase + (size_t)t * Dn + o];
        float y  = g_y[rowbase + (size_t)t * Dn + o];
        #pragma unroll
        for (int s = 0; s < 64; s++) {
            float tmp = __fmul_rn(kk[s], vo);
            Q[s] = fmaf(ww[s], Q[s], tmp);
            y = fmaf(rr[s], fmaf(ue[s], tmp, Q[s]), y);
        }
        g_y[rowbase + (size_t)t * Dn + o] = y;
    }
}

// ---------------- GroupNorm + SiLU gate + LN(4) + act quant ----------------
__global__ void k_gn(const float* __restrict__ gn_g, const float* __restrict__ gn_b,
                     const float* __restrict__ ln_g, const float* __restrict__ ln_b) {
    int row = blockIdx.x;
    int tid = threadIdx.x;
    __shared__ float sz[Dn];
    __shared__ double red[256];

    int head = tid >> 4, sub = tid & 15;
    float yv[4];
    size_t hb = (size_t)row * Dn + head * 64 + sub;
    #pragma unroll
    for (int i = 0; i < 4; i++) yv[i] = g_y[hb + 16 * i];
    double s = (double)yv[0] + (double)yv[1] + (double)yv[2] + (double)yv[3];
    #pragma unroll
    for (int off = 8; off > 0; off >>= 1) s += __shfl_xor_sync(0xffffffffu, s, off, 16);
    float mean = (float)(s * (1.0 / 64.0));
    double s2 = 0.0;
    float dev[4];
    #pragma unroll
    for (int i = 0; i < 4; i++) {
        dev[i] = __fsub_rn(yv[i], mean);
        s2 += (double)__fmul_rn(dev[i], dev[i]);
    }
    #pragma unroll
    for (int off = 8; off > 0; off >>= 1) s2 += __shfl_xor_sync(0xffffffffu, s2, off, 16);
    float var  = (float)(s2 * (1.0 / 64.0));
    float rstd = (float)(1.0 / sqrt((double)__fadd_rn(var, 1e-5f)));
    #pragma unroll
    for (int i = 0; i < 4; i++) {
        int d = head * 64 + sub + 16 * i;
        float yn = __fmul_rn(dev[i], rstd);
        float yg = __fadd_rn(__fmul_rn(yn, gn_g[d]), gn_b[d]);
        float gv = g_rkvg[3][(size_t)row * Dn + d];
        float sig = __fdiv_rn(1.f, __fadd_rn(1.f, expf(-gv)));
        float sil = __fmul_rn(gv, sig);
        sz[d] = __fmul_rn(yg, sil);
    }
    __syncthreads();

    // LayerNorm (variant 4) + act quant
    float inp[4];
    double ssum = 0.0;
    #pragma unroll
    for (int i = 0; i < 4; i++) { int d = tid + i * 256; inp[i] = sz[d]; ssum += (double)inp[i]; }
    float m2 = (float)(blockReduceSumD(ssum, red) * (1.0 / Dn));
    double sv = 0.0;
    float dv[4];
    #pragma unroll
    for (int i = 0; i < 4; i++) {
        dv[i] = __fsub_rn(inp[i], m2);
        sv += (double)__fmul_rn(dv[i], dv[i]);
    }
    float var2 = (float)(blockReduceSumD(sv, red) * (1.0 / Dn));
    float rst2 = (float)(1.0 / sqrt((double)__fadd_rn(var2, 1e-5f)));
    float yln[4];
    double sa = 0.0;
    #pragma unroll
    for (int i = 0; i < 4; i++) {
        int d = tid + i * 256;
        float t1 = __fmul_rn(dv[i], rst2);
        float t2 = __fmul_rn(t1, ln_g[4 * Dn + d]);
        yln[i] = __fadd_rn(t2, ln_b[4 * Dn + d]);
        sa += (double)fabsf(yln[i]);
    }
    float meanabs = (float)(blockReduceSumD(sa, red) * (1.0 / Dn));
    float clipv = __fmul_rn(fmaxf(meanabs, 1e-8f), 2.5f);
    float scale = __fdiv_rn(clipv, 127.f);
    #pragma unroll
    for (int i = 0; i < 4; i++) {
        int d = tid + i * 256;
        float xs = __fdiv_rn(yln[i], scale);
        float xc = fminf(fmaxf(xs, -127.f), 127.f);
        g_zq[(size_t)row * Dn + d] = __fmul_rn(rintf(xc), scale);
    }
}

// ---------------- launch ----------------
extern "C" void kernel_launch(void* const* d_in, const int* in_sizes, int n_in,
                              void* d_out, int out_size) {
    const float* x         = (const float*)d_in[0];
    const float* mu_r      = (const float*)d_in[1];
    const float* mu_k      = (const float*)d_in[2];
    const float* mu_v      = (const float*)d_in[3];
    const float* mu_g      = (const float*)d_in[4];
    const float* log_decay = (const float*)d_in[5];
    const float* u         = (const float*)d_in[6];
    const float* proj_w    = (const float*)d_in[7];
    const float* ln_g      = (const float*)d_in[8];
    const float* ln_b      = (const float*)d_in[9];
    const float* gn_g      = (const float*)d_in[10];
    const float* gn_b      = (const float*)d_in[11];

    float *xqf, *rkvg, *wq, *zq;
    cudaGetSymbolAddress((void**)&xqf,  g_xqf);
    cudaGetSymbolAddress((void**)&rkvg, g_rkvg);
    cudaGetSymbolAddress((void**)&wq,   g_wq);
    cudaGetSymbolAddress((void**)&zq,   g_zq);

    k_params<<<1, 1024>>>(log_decay, u);
    k_wscale<<<5, 256>>>(proj_w);
    k_wquant<<<5 * Dn * Dn / 256, 256>>>(proj_w);
    k_prep<<<BT, 256>>>(x, mu_r, mu_k, mu_v, mu_g, ln_g, ln_b);

    dim3 ggrid(Dn / 128, BT / 128);
    for (int v = 0; v < 4; v++)
        k_gemm<<<ggrid, 256>>>(xqf + (size_t)v * BT * Dn,
                               wq  + (size_t)v * Dn * Dn,
                               rkvg + (size_t)v * BT * Dn);

    k_wkv_local<<<Bn * Hn * NC, 64>>>();
    k_wkv_scan<<<Bn * Hn, 256>>>();
    k_wkv_out<<<Bn * Hn * NC, 64>>>();

    k_gn<<<BT, 256>>>(gn_g, gn_b, ln_g, ln_b);

    k_gemm<<<ggrid, 256>>>(zq, wq + (size_t)4 * Dn * Dn, (float*)d_out);
}

// round 6
// speedup vs baseline: 1.4528x; 1.4528x over previous
#include <cuda_runtime.h>
#include <math.h>

// Problem constants
#define Bn 4
#define Tn 2048
#define Dn 1024
#define Hn 16
#define Sn 64
#define NC 32
#define BT (Bn*Tn)   // 8192 rows

// ---------------- scratch ----------------
__device__ int4  g_xq8[4][BT*Dn/16];    // int8 quantized LN outputs (q values)
__device__ float g_xscale[4][BT];       // per-row act-quant scale
__device__ int4  g_wq8[5][Dn*Dn/16];    // int8 ternary weights
__device__ float g_wscale[5];
__device__ int4  g_zq8[BT*Dn/16];       // int8 quantized gated output
__device__ float g_zscale[BT];
__device__ float g_rkvg[4][BT*Dn];      // projection outputs r,k,v,g (float)
__device__ float g_y[BT*Dn];
__device__ float g_local[Bn*Hn*NC*Sn*Sn];
__device__ float g_init [Bn*Hn*NC*Sn*Sn];
__device__ float g_wpow[65*1024];       // wpow[n][h*64+s] = expf(n*log_w)
__device__ float g_ue[Hn*Sn];

// ---------------- helpers ----------------
__device__ __forceinline__ double blockReduceSumD(double v, double* red) {
    int tid = threadIdx.x;
    red[tid] = v; __syncthreads();
    #pragma unroll
    for (int s = 128; s > 0; s >>= 1) {
        if (tid < s) red[tid] += red[tid + s];
        __syncthreads();
    }
    double r = red[0];
    __syncthreads();
    return r;
}

// ---------------- precompute ----------------
__global__ void k_params(const float* __restrict__ log_decay, const float* __restrict__ u) {
    int i = threadIdx.x;                  // 1024
    float eld = expf(log_decay[i]);
    float wf  = expf(-eld);
    float lw  = logf(fmaxf(wf, 1e-38f));
    for (int n = 0; n <= 64; n++)
        g_wpow[n * 1024 + i] = expf(__fmul_rn((float)n, lw));
    g_ue[i] = expf(u[i]);
}

// ---------------- weight quantization ----------------
__global__ void k_wscale(const float* __restrict__ w) {   // grid 5, block 256
    __shared__ double red[256];
    const float* p = w + (size_t)blockIdx.x * Dn * Dn;
    double s = 0.0;
    for (int i = threadIdx.x; i < Dn * Dn; i += 256) s += (double)fabsf(p[i]);
    double tot = blockReduceSumD(s, red);
    if (threadIdx.x == 0)
        g_wscale[blockIdx.x] = fmaxf((float)(tot / (double)(Dn * Dn)), 1e-8f);
}

__global__ void k_wquant(const float* __restrict__ w) {   // grid 20480, block 256
    int i = blockIdx.x * 256 + threadIdx.x;
    int m = i / (Dn * Dn);
    float s  = g_wscale[m];
    float vn = __fdiv_rn(w[i], s);
    vn = fminf(fmaxf(vn, -1.f), 1.f);
    ((signed char*)g_wq8)[i] = (signed char)(int)rintf(vn);
}

// ---------------- token shift + LN + act quant (int8 out) ----------------
__global__ void k_prep(const float* __restrict__ x,
                       const float* __restrict__ mu_r, const float* __restrict__ mu_k,
                       const float* __restrict__ mu_v, const float* __restrict__ mu_g,
                       const float* __restrict__ ln_g, const float* __restrict__ ln_b) {
    int row = blockIdx.x;           // b*T + t
    int t   = row % Tn;
    int tid = threadIdx.x;
    __shared__ float sx[Dn], sdx[Dn];
    __shared__ double red[256];
    const float* mus[4] = {mu_r, mu_k, mu_v, mu_g};

    #pragma unroll
    for (int i = 0; i < 4; i++) {
        int d = tid + i * 256;
        float xv = x[(size_t)row * Dn + d];
        float xp = (t > 0) ? x[(size_t)(row - 1) * Dn + d] : 0.f;
        sx[d]  = xv;
        sdx[d] = __fsub_rn(xp, xv);
    }
    __syncthreads();

    for (int v = 0; v < 4; v++) {
        const float* mu = mus[v];
        float inp[4];
        double s = 0.0;
        #pragma unroll
        for (int i = 0; i < 4; i++) {
            int d = tid + i * 256;
            inp[i] = __fadd_rn(sx[d], __fmul_rn(sdx[d], mu[d]));
            s += (double)inp[i];
        }
        float mean = (float)(blockReduceSumD(s, red) * (1.0 / Dn));
        double s2 = 0.0;
        float dev[4];
        #pragma unroll
        for (int i = 0; i < 4; i++) {
            dev[i] = __fsub_rn(inp[i], mean);
            s2 += (double)__fmul_rn(dev[i], dev[i]);
        }
        float var  = (float)(blockReduceSumD(s2, red) * (1.0 / Dn));
        float rstd = (float)(1.0 / sqrt((double)__fadd_rn(var, 1e-5f)));
        float yv[4];
        double sa = 0.0;
        #pragma unroll
        for (int i = 0; i < 4; i++) {
            int d = tid + i * 256;
            float t1 = __fmul_rn(dev[i], rstd);
            float t2 = __fmul_rn(t1, ln_g[v * Dn + d]);
            yv[i] = __fadd_rn(t2, ln_b[v * Dn + d]);
            sa += (double)fabsf(yv[i]);
        }
        float meanabs = (float)(blockReduceSumD(sa, red) * (1.0 / Dn));
        float clipv = __fmul_rn(fmaxf(meanabs, 1e-8f), 2.5f);
        float scale = __fdiv_rn(clipv, 127.f);
        if (tid == 0) g_xscale[v][row] = scale;
        #pragma unroll
        for (int i = 0; i < 4; i++) {
            int d = tid + i * 256;
            float xs = __fdiv_rn(yv[i], scale);
            float xc = fminf(fmaxf(xs, -127.f), 127.f);
            ((signed char*)g_xq8[v])[(size_t)row * Dn + d] = (signed char)(int)rintf(xc);
        }
    }
}

// ---------------- int8 DP4A GEMM: C[m,n] = rowscale[m]*ws * sum_k q[m,k]*t[n,k] ----------------
// M=8192, N=K=1024. BM=BN=128, BK=32 bytes, 256 threads, 8x8 per thread.
__global__ void __launch_bounds__(256, 2)
k_gemm8(const int4* __restrict__ A, const int4* __restrict__ W,
        const float* __restrict__ rowscale, const float* __restrict__ wsp,
        float* __restrict__ Cm) {
    __shared__ int As[8][128];
    __shared__ int Bs[8][128];
    int tid = threadIdx.x;
    int m0 = blockIdx.y * 128, n0 = blockIdx.x * 128;
    int lr  = tid >> 1;             // 0..127 row within tile
    int lc4 = tid & 1;              // which 16B half of the 32B chunk
    // row stride in int4 units: 1024 bytes / 16 = 64
    const int4* Ap = A + (size_t)(m0 + lr) * 64 + lc4;
    const int4* Wp = W + (size_t)(n0 + lr) * 64 + lc4;
    int trow = (tid >> 4) << 3;
    int tcol = (tid & 15) << 3;

    int acc[8][8];
    #pragma unroll
    for (int i = 0; i < 8; i++)
        #pragma unroll
        for (int j = 0; j < 8; j++) acc[i][j] = 0;

    for (int kc = 0; kc < 32; kc++) {          // 32 chunks x 32 int8
        int4 a = Ap[kc * 2];
        int4 b = Wp[kc * 2];
        int base = lc4 * 4;
        As[base + 0][lr] = a.x; As[base + 1][lr] = a.y;
        As[base + 2][lr] = a.z; As[base + 3][lr] = a.w;
        Bs[base + 0][lr] = b.x; Bs[base + 1][lr] = b.y;
        Bs[base + 2][lr] = b.z; Bs[base + 3][lr] = b.w;
        __syncthreads();
        #pragma unroll
        for (int kk = 0; kk < 8; kk++) {
            int4 a0 = *(const int4*)&As[kk][trow];
            int4 a1 = *(const int4*)&As[kk][trow + 4];
            int4 b0 = *(const int4*)&Bs[kk][tcol];
            int4 b1 = *(const int4*)&Bs[kk][tcol + 4];
            int ar[8] = {a0.x, a0.y, a0.z, a0.w, a1.x, a1.y, a1.z, a1.w};
            int br[8] = {b0.x, b0.y, b0.z, b0.w, b1.x, b1.y, b1.z, b1.w};
            #pragma unroll
            for (int i = 0; i < 8; i++)
                #pragma unroll
                for (int j = 0; j < 8; j++)
                    acc[i][j] = __dp4a(ar[i], br[j], acc[i][j]);
        }
        __syncthreads();
    }

    float ws = *wsp;
    #pragma unroll
    for (int i = 0; i < 8; i++) {
        float s = __fmul_rn(rowscale[m0 + trow + i], ws);
        float* cp = Cm + (size_t)(m0 + trow + i) * Dn + n0 + tcol;
        float c0x = __fmul_rn((float)acc[i][0], s);
        float c0y = __fmul_rn((float)acc[i][1], s);
        float c0z = __fmul_rn((float)acc[i][2], s);
        float c0w = __fmul_rn((float)acc[i][3], s);
        float c1x = __fmul_rn((float)acc[i][4], s);
        float c1y = __fmul_rn((float)acc[i][5], s);
        float c1z = __fmul_rn((float)acc[i][6], s);
        float c1w = __fmul_rn((float)acc[i][7], s);
        float4 c0 = {c0x, c0y, c0z, c0w};
        float4 c1 = {c1x, c1y, c1z, c1w};
        *(float4*)cp       = c0;
        *(float4*)(cp + 4) = c1;
    }
}

// ---------------- WKV phase 1 ----------------
__global__ void k_wkv_local() {
    int o = threadIdx.x;            // 64
    int idx = blockIdx.x;           // 2048
    int c = idx & 31, h = (idx >> 5) & 15, b = idx >> 9;
    const float* kbuf = g_rkvg[1];
    const float* vbuf = g_rkvg[2];
    __shared__ float kk[64], drow[64];
    float ls[64];
    #pragma unroll
    for (int s = 0; s < 64; s++) ls[s] = 0.f;
    size_t rowbase = (size_t)(b * Tn + c * 64) * Dn + h * 64;
    for (int t = 0; t < 64; t++) {
        __syncthreads();
        kk[o]   = kbuf[rowbase + (size_t)t * Dn + o];
        drow[o] = g_wpow[(63 - t) * 1024 + h * 64 + o];
        __syncthreads();
        float vo = vbuf[rowbase + (size_t)t * Dn + o];
        #pragma unroll
        for (int s = 0; s < 64; s++)
            ls[s] = fmaf(drow[s], __fmul_rn(kk[s], vo), ls[s]);
    }
    float* lp = g_local + (size_t)idx * 4096;
    #pragma unroll
    for (int s = 0; s < 64; s++) lp[s * 64 + o] = ls[s];
}

// ---------------- WKV phase 2 ----------------
__global__ void k_wkv_scan() {      // grid 64, block 256
    int bh = blockIdx.x;
    int h  = bh & 15;
    int tid = threadIdx.x;
    float cur[16], wc[16];
    #pragma unroll
    for (int j = 0; j < 16; j++) {
        cur[j] = 0.f;
        int e = tid + j * 256;
        wc[j] = g_wpow[64 * 1024 + h * 64 + (e >> 6)];
    }
    for (int c = 0; c < NC; c++) {
        size_t base = ((size_t)bh * NC + c) * 4096;
        #pragma unroll
        for (int j = 0; j < 16; j++) {
            int e = tid + j * 256;
            g_init[base + e] = cur[j];
            cur[j] = __fadd_rn(__fmul_rn(wc[j], cur[j]), g_local[base + e]);
        }
    }
}

// ---------------- WKV phase 3 ----------------
__global__ void k_wkv_out() {
    int o = threadIdx.x;            // 64
    int idx = blockIdx.x;           // 2048
    int c = idx & 31, h = (idx >> 5) & 15, b = idx >> 9;
    __shared__ float kk[64], rr[64], ww[64], ue[64], crow[64];
    ww[o] = g_wpow[1024 + h * 64 + o];
    ue[o] = g_ue[h * 64 + o];
    size_t rowbase = (size_t)(b * Tn + c * 64) * Dn + h * 64;

    // Pass A: y_t = r . (wpow[t+1] * S0)
    float A0[64];
    const float* ip = g_init + (size_t)idx * 4096;
    #pragma unroll
    for (int s = 0; s < 64; s++) A0[s] = ip[s * 64 + o];
    for (int t = 0; t < 64; t++) {
        __syncthreads();
        rr[o]   = g_rkvg[0][rowbase + (size_t)t * Dn + o];
        crow[o] = g_wpow[(t + 1) * 1024 + h * 64 + o];
        __syncthreads();
        float y = 0.f;
        #pragma unroll
        for (int s = 0; s < 64; s++)
            y = fmaf(rr[s], __fmul_rn(crow[s], A0[s]), y);
        g_y[rowbase + (size_t)t * Dn + o] = y;
    }

    // Pass B: backward Q recurrence + bonus
    float Q[64];
    #pragma unroll
    for (int s = 0; s < 64; s++) Q[s] = 0.f;
    for (int t = 63; t >= 0; t--) {
        __syncthreads();
        kk[o] = g_rkvg[1][rowbase + (size_t)t * Dn + o];
        rr[o] = g_rkvg[0][rowbase + (size_t)t * Dn + o];
        __syncthreads();
        float vo = g_rkvg[2][rowbase + (size_t)t * Dn + o];
        float y  = g_y[rowbase + (size_t)t * Dn + o];
        #pragma unroll
        for (int s = 0; s < 64; s++) {
            float tmp = __fmul_rn(kk[s], vo);
            Q[s] = fmaf(ww[s], Q[s], tmp);
            y = fmaf(rr[s], fmaf(ue[s], tmp, Q[s]), y);
        }
        g_y[rowbase + (size_t)t * Dn + o] = y;
    }
}

// ---------------- GroupNorm + SiLU + LN(4) + act quant (int8 out) ----------------
__global__ void k_gn(const float* __restrict__ gn_g, const float* __restrict__ gn_b,
                     const float* __restrict__ ln_g, const float* __restrict__ ln_b) {
    int row = blockIdx.x;
    int tid = threadIdx.x;
    __shared__ float sz[Dn];
    __shared__ double red[256];

    int head = tid >> 4, sub = tid & 15;
    float yv[4];
    size_t hb = (size_t)row * Dn + head * 64 + sub;
    #pragma unroll
    for (int i = 0; i < 4; i++) yv[i] = g_y[hb + 16 * i];
    double s = (double)yv[0] + (double)yv[1] + (double)yv[2] + (double)yv[3];
    #pragma unroll
    for (int off = 8; off > 0; off >>= 1) s += __shfl_xor_sync(0xffffffffu, s, off, 16);
    float mean = (float)(s * (1.0 / 64.0));
    double s2 = 0.0;
    float dev[4];
    #pragma unroll
    for (int i = 0; i < 4; i++) {
        dev[i] = __fsub_rn(yv[i], mean);
        s2 += (double)__fmul_rn(dev[i], dev[i]);
    }
    #pragma unroll
    for (int off = 8; off > 0; off >>= 1) s2 += __shfl_xor_sync(0xffffffffu, s2, off, 16);
    float var  = (float)(s2 * (1.0 / 64.0));
    float rstd = (float)(1.0 / sqrt((double)__fadd_rn(var, 1e-5f)));
    #pragma unroll
    for (int i = 0; i < 4; i++) {
        int d = head * 64 + sub + 16 * i;
        float yn = __fmul_rn(dev[i], rstd);
        float yg = __fadd_rn(__fmul_rn(yn, gn_g[d]), gn_b[d]);
        float gv = g_rkvg[3][(size_t)row * Dn + d];
        float sig = __fdiv_rn(1.f, __fadd_rn(1.f, expf(-gv)));
        float sil = __fmul_rn(gv, sig);
        sz[d] = __fmul_rn(yg, sil);
    }
    __syncthreads();

    float inp[4];
    double ssum = 0.0;
    #pragma unroll
    for (int i = 0; i < 4; i++) { int d = tid + i * 256; inp[i] = sz[d]; ssum += (double)inp[i]; }
    float m2 = (float)(blockReduceSumD(ssum, red) * (1.0 / Dn));
    double sv = 0.0;
    float dv[4];
    #pragma unroll
    for (int i = 0; i < 4; i++) {
        dv[i] = __fsub_rn(inp[i], m2);
        sv += (double)__fmul_rn(dv[i], dv[i]);
    }
    float var2 = (float)(blockReduceSumD(sv, red) * (1.0 / Dn));
    float rst2 = (float)(1.0 / sqrt((double)__fadd_rn(var2, 1e-5f)));
    float yln[4];
    double sa = 0.0;
    #pragma unroll
    for (int i = 0; i < 4; i++) {
        int d = tid + i * 256;
        float t1 = __fmul_rn(dv[i], rst2);
        float t2 = __fmul_rn(t1, ln_g[4 * Dn + d]);
        yln[i] = __fadd_rn(t2, ln_b[4 * Dn + d]);
        sa += (double)fabsf(yln[i]);
    }
    float meanabs = (float)(blockReduceSumD(sa, red) * (1.0 / Dn));
    float clipv = __fmul_rn(fmaxf(meanabs, 1e-8f), 2.5f);
    float scale = __fdiv_rn(clipv, 127.f);
    if (tid == 0) g_zscale[row] = scale;
    #pragma unroll
    for (int i = 0; i < 4; i++) {
        int d = tid + i * 256;
        float xs = __fdiv_rn(yln[i], scale);
        float xc = fminf(fmaxf(xs, -127.f), 127.f);
        ((signed char*)g_zq8)[(size_t)row * Dn + d] = (signed char)(int)rintf(xc);
    }
}

// ---------------- launch ----------------
extern "C" void kernel_launch(void* const* d_in, const int* in_sizes, int n_in,
                              void* d_out, int out_size) {
    const float* x         = (const float*)d_in[0];
    const float* mu_r      = (const float*)d_in[1];
    const float* mu_k      = (const float*)d_in[2];
    const float* mu_v      = (const float*)d_in[3];
    const float* mu_g      = (const float*)d_in[4];
    const float* log_decay = (const float*)d_in[5];
    const float* u         = (const float*)d_in[6];
    const float* proj_w    = (const float*)d_in[7];
    const float* ln_g      = (const float*)d_in[8];
    const float* ln_b      = (const float*)d_in[9];
    const float* gn_g      = (const float*)d_in[10];
    const float* gn_b      = (const float*)d_in[11];

    int4 *xq8, *wq8, *zq8;
    float *rkvg, *xscale, *zscale, *wscale;
    cudaGetSymbolAddress((void**)&xq8,    g_xq8);
    cudaGetSymbolAddress((void**)&wq8,    g_wq8);
    cudaGetSymbolAddress((void**)&zq8,    g_zq8);
    cudaGetSymbolAddress((void**)&rkvg,   g_rkvg);
    cudaGetSymbolAddress((void**)&xscale, g_xscale);
    cudaGetSymbolAddress((void**)&zscale, g_zscale);
    cudaGetSymbolAddress((void**)&wscale, g_wscale);

    k_params<<<1, 1024>>>(log_decay, u);
    k_wscale<<<5, 256>>>(proj_w);
    k_wquant<<<5 * Dn * Dn / 256, 256>>>(proj_w);
    k_prep<<<BT, 256>>>(x, mu_r, mu_k, mu_v, mu_g, ln_g, ln_b);

    dim3 ggrid(Dn / 128, BT / 128);
    for (int v = 0; v < 4; v++)
        k_gemm8<<<ggrid, 256>>>(xq8 + (size_t)v * (BT * Dn / 16),
                                wq8 + (size_t)v * (Dn * Dn / 16),
                                xscale + (size_t)v * BT,
                                wscale + v,
                                rkvg + (size_t)v * BT * Dn);

    k_wkv_local<<<Bn * Hn * NC, 64>>>();
    k_wkv_scan<<<Bn * Hn, 256>>>();
    k_wkv_out<<<Bn * Hn * NC, 64>>>();

    k_gn<<<BT, 256>>>(gn_g, gn_b, ln_g, ln_b);

    k_gemm8<<<ggrid, 256>>>(zq8, wq8 + (size_t)4 * (Dn * Dn / 16),
                            zscale, wscale + 4, (float*)d_out);
}

// round 8
// speedup vs baseline: 1.4983x; 1.0313x over previous
#include <cuda_runtime.h>
#include <math.h>
#include <stdint.h>

// Problem constants
#define Bn 4
#define Tn 2048
#define Dn 1024
#define Hn 16
#define Sn 64
#define NC 32
#define BT (Bn*Tn)   // 8192 rows

// ---------------- scratch ----------------
__device__ int4  g_xq8[4][BT*Dn/16];    // int8 quantized LN outputs
__device__ float g_xscale[4][BT];
__device__ int4  g_wq8[5][Dn*Dn/16];    // int8 ternary weights
__device__ float g_wscale[5];
__device__ int4  g_zq8[BT*Dn/16];
__device__ float g_zscale[BT];
__device__ float g_rkvg[4][BT*Dn];
__device__ float g_y[BT*Dn];
__device__ float g_local[Bn*Hn*NC*Sn*Sn];
__device__ float g_init [Bn*Hn*NC*Sn*Sn];
__device__ float g_wpow[65*1024];
__device__ float g_ue[Hn*Sn];

// ---------------- helpers ----------------
__device__ __forceinline__ double blockReduceSumD(double v, double* red) {
    int tid = threadIdx.x;
    red[tid] = v; __syncthreads();
    #pragma unroll
    for (int s = 128; s > 0; s >>= 1) {
        if (tid < s) red[tid] += red[tid + s];
        __syncthreads();
    }
    double r = red[0];
    __syncthreads();
    return r;
}

__device__ __forceinline__ uint32_t smem_u32(const void* p) {
    uint32_t a;
    asm("{ .reg .u64 t; cvta.to.shared.u64 t, %1; cvt.u32.u64 %0, t; }" : "=r"(a) : "l"(p));
    return a;
}
__device__ __forceinline__ void cp16(uint32_t dst, const void* src) {
    asm volatile("cp.async.cg.shared.global [%0], [%1], 16;" :: "r"(dst), "l"(src) : "memory");
}
#define CPCOMMIT()  asm volatile("cp.async.commit_group;" ::: "memory")
#define CPWAIT1()   asm volatile("cp.async.wait_group 1;" ::: "memory")
#define CPWAIT0()   asm volatile("cp.async.wait_group 0;" ::: "memory")
#define LDSM4(r, addr) \
    asm volatile("ldmatrix.sync.aligned.m8n8.x4.shared.b16 {%0,%1,%2,%3}, [%4];" \
        : "=r"((r)[0]), "=r"((r)[1]), "=r"((r)[2]), "=r"((r)[3]) : "r"(addr))
#define MMA8(c, a, b0, b1) \
    asm volatile("mma.sync.aligned.m16n8k32.row.col.s32.s8.s8.s32 " \
        "{%0,%1,%2,%3}, {%4,%5,%6,%7}, {%8,%9}, {%0,%1,%2,%3};" \
        : "+r"((c)[0]), "+r"((c)[1]), "+r"((c)[2]), "+r"((c)[3]) \
        : "r"((a)[0]), "r"((a)[1]), "r"((a)[2]), "r"((a)[3]), "r"(b0), "r"(b1))

// ---------------- precompute ----------------
__global__ void k_params(const float* __restrict__ log_decay, const float* __restrict__ u) {
    int i = threadIdx.x;
    float eld = expf(log_decay[i]);
    float wf  = expf(-eld);
    float lw  = logf(fmaxf(wf, 1e-38f));
    for (int n = 0; n <= 64; n++)
        g_wpow[n * 1024 + i] = expf(__fmul_rn((float)n, lw));
    g_ue[i] = expf(u[i]);
}

// ---------------- weight quantization ----------------
__global__ void k_wscale(const float* __restrict__ w) {
    __shared__ double red[256];
    const float* p = w + (size_t)blockIdx.x * Dn * Dn;
    double s = 0.0;
    for (int i = threadIdx.x; i < Dn * Dn; i += 256) s += (double)fabsf(p[i]);
    double tot = blockReduceSumD(s, red);
    if (threadIdx.x == 0)
        g_wscale[blockIdx.x] = fmaxf((float)(tot / (double)(Dn * Dn)), 1e-8f);
}

__global__ void k_wquant(const float* __restrict__ w) {
    int i = blockIdx.x * 256 + threadIdx.x;
    int m = i / (Dn * Dn);
    float s  = g_wscale[m];
    float vn = __fdiv_rn(w[i], s);
    vn = fminf(fmaxf(vn, -1.f), 1.f);
    ((signed char*)g_wq8)[i] = (signed char)(int)rintf(vn);
}

// ---------------- token shift + LN + act quant (int8 out) ----------------
__global__ void k_prep(const float* __restrict__ x,
                       const float* __restrict__ mu_r, const float* __restrict__ mu_k,
                       const float* __restrict__ mu_v, const float* __restrict__ mu_g,
                       const float* __restrict__ ln_g, const float* __restrict__ ln_b) {
    int row = blockIdx.x;
    int t   = row % Tn;
    int tid = threadIdx.x;
    __shared__ float sx[Dn], sdx[Dn];
    __shared__ double red[256];
    const float* mus[4] = {mu_r, mu_k, mu_v, mu_g};

    #pragma unroll
    for (int i = 0; i < 4; i++) {
        int d = tid + i * 256;
        float xv = x[(size_t)row * Dn + d];
        float xp = (t > 0) ? x[(size_t)(row - 1) * Dn + d] : 0.f;
        sx[d]  = xv;
        sdx[d] = __fsub_rn(xp, xv);
    }
    __syncthreads();

    for (int v = 0; v < 4; v++) {
        const float* mu = mus[v];
        float inp[4];
        double s = 0.0;
        #pragma unroll
        for (int i = 0; i < 4; i++) {
            int d = tid + i * 256;
            inp[i] = __fadd_rn(sx[d], __fmul_rn(sdx[d], mu[d]));
            s += (double)inp[i];
        }
        float mean = (float)(blockReduceSumD(s, red) * (1.0 / Dn));
        double s2 = 0.0;
        float dev[4];
        #pragma unroll
        for (int i = 0; i < 4; i++) {
            dev[i] = __fsub_rn(inp[i], mean);
            s2 += (double)__fmul_rn(dev[i], dev[i]);
        }
        float var  = (float)(blockReduceSumD(s2, red) * (1.0 / Dn));
        float rstd = (float)(1.0 / sqrt((double)__fadd_rn(var, 1e-5f)));
        float yv[4];
        double sa = 0.0;
        #pragma unroll
        for (int i = 0; i < 4; i++) {
            int d = tid + i * 256;
            float t1 = __fmul_rn(dev[i], rstd);
            float t2 = __fmul_rn(t1, ln_g[v * Dn + d]);
            yv[i] = __fadd_rn(t2, ln_b[v * Dn + d]);
            sa += (double)fabsf(yv[i]);
        }
        float meanabs = (float)(blockReduceSumD(sa, red) * (1.0 / Dn));
        float clipv = __fmul_rn(fmaxf(meanabs, 1e-8f), 2.5f);
        float scale = __fdiv_rn(clipv, 127.f);
        if (tid == 0) g_xscale[v][row] = scale;
        #pragma unroll
        for (int i = 0; i < 4; i++) {
            int d = tid + i * 256;
            float xs = __fdiv_rn(yv[i], scale);
            float xc = fminf(fmaxf(xs, -127.f), 127.f);
            ((signed char*)g_xq8[v])[(size_t)row * Dn + d] = (signed char)(int)rintf(xc);
        }
    }
}

// ---------------- int8 tensor-core GEMM via mma.sync (exact int32 accum) ----------------
// C[m,n] = rowscale[m]*ws * sum_k q[m,k]*t[n,k];  M=8192, N=K=1024.
// CTA 128x128, 8 warps (2x4), warp tile 64x32. K chunks of 64B, cp.async double buffer.
// smem rows padded to 80B: 16B-chunk bank index (5r+c) mod 8 -> ldmatrix conflict-free.
#define ROWB 80
__global__ void __launch_bounds__(256, 2)
k_gemm_i8(const int4* __restrict__ A, const int4* __restrict__ W,
          const float* __restrict__ rowscale, const float* __restrict__ wsp,
          float* __restrict__ Cm) {
    __shared__ __align__(16) signed char As[2][128 * ROWB];
    __shared__ __align__(16) signed char Bs[2][128 * ROWB];
    int tid = threadIdx.x, lid = tid & 31, wid = tid >> 5;
    int m0 = blockIdx.y * 128, n0 = blockIdx.x * 128;
    int wm = (wid & 1) * 64, wn = (wid >> 1) * 32;

    // loader: thread -> row tid>>1, 2 consecutive 16B chunks (tid&1)*2..+1
    int lrow = tid >> 1;
    int lc   = (tid & 1) * 2;
    const int4* Ag = A + (size_t)(m0 + lrow) * 64 + lc;   // 64 int4 per gmem row
    const int4* Wg = W + (size_t)(n0 + lrow) * 64 + lc;
    uint32_t soff = (uint32_t)(lrow * ROWB + lc * 16);
    uint32_t sa[2] = {smem_u32(As[0]), smem_u32(As[1])};
    uint32_t sbm[2] = {smem_u32(Bs[0]), smem_u32(Bs[1])};

    // ldmatrix per-lane base addresses
    int arow   = (lid & 7) + ((lid >> 3) & 1) * 8;   // a0/a1/a2/a3 tile rows
    int akhalf = lid >> 4;                            // k bytes 0-15 vs 16-31
    int brow   = (lid & 7) + (lid >> 4) * 8;          // ntile pair rows
    int bkhalf = (lid >> 3) & 1;
    uint32_t aaddr[2][4], baddr[2][2];
    #pragma unroll
    for (int buf = 0; buf < 2; buf++) {
        #pragma unroll
        for (int mt = 0; mt < 4; mt++)
            aaddr[buf][mt] = sa[buf] + (uint32_t)((wm + mt * 16 + arow) * ROWB + akhalf * 16);
        #pragma unroll
        for (int bt = 0; bt < 2; bt++)
            baddr[buf][bt] = sbm[buf] + (uint32_t)((wn + bt * 16 + brow) * ROWB + bkhalf * 16);
    }

    int c[4][4][4];
    #pragma unroll
    for (int mt = 0; mt < 4; mt++)
        #pragma unroll
        for (int nt = 0; nt < 4; nt++)
            #pragma unroll
            for (int q = 0; q < 4; q++) c[mt][nt][q] = 0;

    // prologue: chunk 0 -> buf 0
    cp16(sa[0] + soff,       Ag);
    cp16(sa[0] + soff + 16,  Ag + 1);
    cp16(sbm[0] + soff,      Wg);
    cp16(sbm[0] + soff + 16, Wg + 1);
    CPCOMMIT();

    for (int kb = 0; kb < 16; kb++) {
        int buf = kb & 1;
        if (kb < 15) {
            const int4* an = Ag + (kb + 1) * 4;
            const int4* wn_ = Wg + (kb + 1) * 4;
            int nb = buf ^ 1;
            cp16(sa[nb] + soff,       an);
            cp16(sa[nb] + soff + 16,  an + 1);
            cp16(sbm[nb] + soff,      wn_);
            cp16(sbm[nb] + soff + 16, wn_ + 1);
            CPCOMMIT();
            CPWAIT1();
        } else {
            CPWAIT0();
        }
        __syncthreads();

        #pragma unroll
        for (int ks = 0; ks < 2; ks++) {
            uint32_t af[4][4], bf[2][4];
            #pragma unroll
            for (int mt = 0; mt < 4; mt++) LDSM4(af[mt], aaddr[buf][mt] + ks * 32);
            #pragma unroll
            for (int bt = 0; bt < 2; bt++) LDSM4(bf[bt], baddr[buf][bt] + ks * 32);
            #pragma unroll
            for (int mt = 0; mt < 4; mt++)
                #pragma unroll
                for (int nt = 0; nt < 4; nt++)
                    MMA8(c[mt][nt], af[mt], bf[nt >> 1][(nt & 1) * 2], bf[nt >> 1][(nt & 1) * 2 + 1]);
        }
        __syncthreads();
    }

    // epilogue
    float ws = *wsp;
    int g = lid >> 2, t4 = lid & 3;
    #pragma unroll
    for (int mt = 0; mt < 4; mt++) {
        int row = m0 + wm + mt * 16 + g;
        float rs0 = __fmul_rn(rowscale[row], ws);
        float rs1 = __fmul_rn(rowscale[row + 8], ws);
        float* cp0 = Cm + (size_t)row * Dn + n0 + wn;
        float* cp1 = cp0 + (size_t)8 * Dn;
        #pragma unroll
        for (int nt = 0; nt < 4; nt++) {
            int col = nt * 8 + t4 * 2;
            float2 v0, v1;
            v0.x = __fmul_rn((float)c[mt][nt][0], rs0);
            v0.y = __fmul_rn((float)c[mt][nt][1], rs0);
            v1.x = __fmul_rn((float)c[mt][nt][2], rs1);
            v1.y = __fmul_rn((float)c[mt][nt][3], rs1);
            *(float2*)(cp0 + col) = v0;
            *(float2*)(cp1 + col) = v1;
        }
    }
}

// ---------------- WKV phase 1 ----------------
__global__ void k_wkv_local() {
    int o = threadIdx.x;
    int idx = blockIdx.x;
    int c = idx & 31, h = (idx >> 5) & 15, b = idx >> 9;
    const float* kbuf = g_rkvg[1];
    const float* vbuf = g_rkvg[2];
    __shared__ float kk[64], drow[64];
    float ls[64];
    #pragma unroll
    for (int s = 0; s < 64; s++) ls[s] = 0.f;
    size_t rowbase = (size_t)(b * Tn + c * 64) * Dn + h * 64;
    for (int t = 0; t < 64; t++) {
        __syncthreads();
        kk[o]   = kbuf[rowbase + (size_t)t * Dn + o];
        drow[o] = g_wpow[(63 - t) * 1024 + h * 64 + o];
        __syncthreads();
        float vo = vbuf[rowbase + (size_t)t * Dn + o];
        #pragma unroll
        for (int s = 0; s < 64; s++)
            ls[s] = fmaf(drow[s], __fmul_rn(kk[s], vo), ls[s]);
    }
    float* lp = g_local + (size_t)idx * 4096;
    #pragma unroll
    for (int s = 0; s < 64; s++) lp[s * 64 + o] = ls[s];
}

// ---------------- WKV phase 2 ----------------
__global__ void k_wkv_scan() {
    int bh = blockIdx.x;
    int h  = bh & 15;
    int tid = threadIdx.x;
    float cur[16], wc[16];
    #pragma unroll
    for (int j = 0; j < 16; j++) {
        cur[j] = 0.f;
        int e = tid + j * 256;
        wc[j] = g_wpow[64 * 1024 + h * 64 + (e >> 6)];
    }
    for (int c = 0; c < NC; c++) {
        size_t base = ((size_t)bh * NC + c) * 4096;
        #pragma unroll
        for (int j = 0; j < 16; j++) {
            int e = tid + j * 256;
            g_init[base + e] = cur[j];
            cur[j] = __fadd_rn(__fmul_rn(wc[j], cur[j]), g_local[base + e]);
        }
    }
}

// ---------------- WKV phase 3 ----------------
__global__ void k_wkv_out() {
    int o = threadIdx.x;
    int idx = blockIdx.x;
    int c = idx & 31, h = (idx >> 5) & 15, b = idx >> 9;
    __shared__ float kk[64], rr[64], ww[64], ue[64], crow[64];
    ww[o] = g_wpow[1024 + h * 64 + o];
    ue[o] = g_ue[h * 64 + o];
    size_t rowbase = (size_t)(b * Tn + c * 64) * Dn + h * 64;

    float A0[64];
    const float* ip = g_init + (size_t)idx * 4096;
    #pragma unroll
    for (int s = 0; s < 64; s++) A0[s] = ip[s * 64 + o];
    for (int t = 0; t < 64; t++) {
        __syncthreads();
        rr[o]   = g_rkvg[0][rowbase + (size_t)t * Dn + o];
        crow[o] = g_wpow[(t + 1) * 1024 + h * 64 + o];
        __syncthreads();
        float y = 0.f;
        #pragma unroll
        for (int s = 0; s < 64; s++)
            y = fmaf(rr[s], __fmul_rn(crow[s], A0[s]), y);
        g_y[rowbase + (size_t)t * Dn + o] = y;
    }

    float Q[64];
    #pragma unroll
    for (int s = 0; s < 64; s++) Q[s] = 0.f;
    for (int t = 63; t >= 0; t--) {
        __syncthreads();
        kk[o] = g_rkvg[1][rowbase + (size_t)t * Dn + o];
        rr[o] = g_rkvg[0][rowbase + (size_t)t * Dn + o];
        __syncthreads();
        float vo = g_rkvg[2][rowbase + (size_t)t * Dn + o];
        float y  = g_y[rowbase + (size_t)t * Dn + o];
        #pragma unroll
        for (int s = 0; s < 64; s++) {
            float tmp = __fmul_rn(kk[s], vo);
            Q[s] = fmaf(ww[s], Q[s], tmp);
            y = fmaf(rr[s], fmaf(ue[s], tmp, Q[s]), y);
        }
        g_y[rowbase + (size_t)t * Dn + o] = y;
    }
}

// ---------------- GroupNorm + SiLU + LN(4) + act quant (int8 out) ----------------
__global__ void k_gn(const float* __restrict__ gn_g, const float* __restrict__ gn_b,
                     const float* __restrict__ ln_g, const float* __restrict__ ln_b) {
    int row = blockIdx.x;
    int tid = threadIdx.x;
    __shared__ float sz[Dn];
    __shared__ double red[256];

    int head = tid >> 4, sub = tid & 15;
    float yv[4];
    size_t hb = (size_t)row * Dn + head * 64 + sub;
    #pragma unroll
    for (int i = 0; i < 4; i++) yv[i] = g_y[hb + 16 * i];
    double s = (double)yv[0] + (double)yv[1] + (double)yv[2] + (double)yv[3];
    #pragma unroll
    for (int off = 8; off > 0; off >>= 1) s += __shfl_xor_sync(0xffffffffu, s, off, 16);
    float mean = (float)(s * (1.0 / 64.0));
    double s2 = 0.0;
    float dev[4];
    #pragma unroll
    for (int i = 0; i < 4; i++) {
        dev[i] = __fsub_rn(yv[i], mean);
        s2 += (double)__fmul_rn(dev[i], dev[i]);
    }
    #pragma unroll
    for (int off = 8; off > 0; off >>= 1) s2 += __shfl_xor_sync(0xffffffffu, s2, off, 16);
    float var  = (float)(s2 * (1.0 / 64.0));
    float rstd = (float)(1.0 / sqrt((double)__fadd_rn(var, 1e-5f)));
    #pragma unroll
    for (int i = 0; i < 4; i++) {
        int d = head * 64 + sub + 16 * i;
        float yn = __fmul_rn(dev[i], rstd);
        float yg = __fadd_rn(__fmul_rn(yn, gn_g[d]), gn_b[d]);
        float gv = g_rkvg[3][(size_t)row * Dn + d];
        float sig = __fdiv_rn(1.f, __fadd_rn(1.f, expf(-gv)));
        float sil = __fmul_rn(gv, sig);
        sz[d] = __fmul_rn(yg, sil);
    }
    __syncthreads();

    float inp[4];
    double ssum = 0.0;
    #pragma unroll
    for (int i = 0; i < 4; i++) { int d = tid + i * 256; inp[i] = sz[d]; ssum += (double)inp[i]; }
    float m2 = (float)(blockReduceSumD(ssum, red) * (1.0 / Dn));
    double sv = 0.0;
    float dv[4];
    #pragma unroll
    for (int i = 0; i < 4; i++) {
        dv[i] = __fsub_rn(inp[i], m2);
        sv += (double)__fmul_rn(dv[i], dv[i]);
    }
    float var2 = (float)(blockReduceSumD(sv, red) * (1.0 / Dn));
    float rst2 = (float)(1.0 / sqrt((double)__fadd_rn(var2, 1e-5f)));
    float yln[4];
    double sa = 0.0;
    #pragma unroll
    for (int i = 0; i < 4; i++) {
        int d = tid + i * 256;
        float t1 = __fmul_rn(dv[i], rst2);
        float t2 = __fmul_rn(t1, ln_g[4 * Dn + d]);
        yln[i] = __fadd_rn(t2, ln_b[4 * Dn + d]);
        sa += (double)fabsf(yln[i]);
    }
    float meanabs = (float)(blockReduceSumD(sa, red) * (1.0 / Dn));
    float clipv = __fmul_rn(fmaxf(meanabs, 1e-8f), 2.5f);
    float scale = __fdiv_rn(clipv, 127.f);
    if (tid == 0) g_zscale[row] = scale;
    #pragma unroll
    for (int i = 0; i < 4; i++) {
        int d = tid + i * 256;
        float xs = __fdiv_rn(yln[i], scale);
        float xc = fminf(fmaxf(xs, -127.f), 127.f);
        ((signed char*)g_zq8)[(size_t)row * Dn + d] = (signed char)(int)rintf(xc);
    }
}

// ---------------- launch ----------------
extern "C" void kernel_launch(void* const* d_in, const int* in_sizes, int n_in,
                              void* d_out, int out_size) {
    const float* x         = (const float*)d_in[0];
    const float* mu_r      = (const float*)d_in[1];
    const float* mu_k      = (const float*)d_in[2];
    const float* mu_v      = (const float*)d_in[3];
    const float* mu_g      = (const float*)d_in[4];
    const float* log_decay = (const float*)d_in[5];
    const float* u         = (const float*)d_in[6];
    const float* proj_w    = (const float*)d_in[7];
    const float* ln_g      = (const float*)d_in[8];
    const float* ln_b      = (const float*)d_in[9];
    const float* gn_g      = (const float*)d_in[10];
    const float* gn_b      = (const float*)d_in[11];

    int4 *xq8, *wq8, *zq8;
    float *rkvg, *xscale, *zscale, *wscale;
    cudaGetSymbolAddress((void**)&xq8,    g_xq8);
    cudaGetSymbolAddress((void**)&wq8,    g_wq8);
    cudaGetSymbolAddress((void**)&zq8,    g_zq8);
    cudaGetSymbolAddress((void**)&rkvg,   g_rkvg);
    cudaGetSymbolAddress((void**)&xscale, g_xscale);
    cudaGetSymbolAddress((void**)&zscale, g_zscale);
    cudaGetSymbolAddress((void**)&wscale, g_wscale);

    k_params<<<1, 1024>>>(log_decay, u);
    k_wscale<<<5, 256>>>(proj_w);
    k_wquant<<<5 * Dn * Dn / 256, 256>>>(proj_w);
    k_prep<<<BT, 256>>>(x, mu_r, mu_k, mu_v, mu_g, ln_g, ln_b);

    dim3 ggrid(Dn / 128, BT / 128);
    for (int v = 0; v < 4; v++)
        k_gemm_i8<<<ggrid, 256>>>(xq8 + (size_t)v * (BT * Dn / 16),
                                  wq8 + (size_t)v * (Dn * Dn / 16),
                                  xscale + (size_t)v * BT,
                                  wscale + v,
                                  rkvg + (size_t)v * BT * Dn);

    k_wkv_local<<<Bn * Hn * NC, 64>>>();
    k_wkv_scan<<<Bn * Hn, 256>>>();
    k_wkv_out<<<Bn * Hn * NC, 64>>>();

    k_gn<<<BT, 256>>>(gn_g, gn_b, ln_g, ln_b);

    k_gemm_i8<<<ggrid, 256>>>(zq8, wq8 + (size_t)4 * (Dn * Dn / 16),
                              zscale, wscale + 4, (float*)d_out);
}

// round 13
// speedup vs baseline: 1.5513x; 1.0354x over previous
#include <cuda_runtime.h>
#include <math.h>
#include <stdint.h>

// Problem constants
#define Bn 4
#define Tn 2048
#define Dn 1024
#define Hn 16
#define Sn 64
#define NC 32
#define BT (Bn*Tn)   // 8192 rows

typedef unsigned long long u64;

// ---------------- scratch ----------------
__device__ int4  g_xq8[4][BT*Dn/16];
__device__ float g_xscale[4][BT];
__device__ int4  g_wq8[5][Dn*Dn/16];
__device__ float g_wscale[5];
__device__ int4  g_zq8[BT*Dn/16];
__device__ float g_zscale[BT];
__device__ float g_rkvg[4][BT*Dn];
__device__ float g_y[BT*Dn];
__device__ float g_local[Bn*Hn*NC*Sn*Sn];
__device__ float g_init [Bn*Hn*NC*Sn*Sn];
__device__ float g_wpow[65*1024];
__device__ float g_ue[Hn*Sn];

// ---------------- f32x2 packed helpers ----------------
#define F2MUL(d, a, b)    asm("mul.rn.f32x2 %0, %1, %2;" : "=l"(d) : "l"(a), "l"(b))
#define F2FMA(d, a, b, c) asm("fma.rn.f32x2 %0, %1, %2, %3;" : "=l"(d) : "l"(a), "l"(b), "l"(c))
__device__ __forceinline__ u64 pk(float x, float y) {
    u64 r; asm("mov.b64 %0, {%1, %2};" : "=l"(r) : "f"(x), "f"(y)); return r;
}

// ---------------- block reduce (warp-shuffle, fp64) ----------------
__device__ __forceinline__ double brD(double v, double* red) {
    int tid = threadIdx.x, lane = tid & 31, wid = tid >> 5;
    int nw = blockDim.x >> 5;
    #pragma unroll
    for (int o = 16; o; o >>= 1) v += __shfl_xor_sync(0xffffffffu, v, o);
    if (lane == 0) red[wid] = v;
    __syncthreads();
    if (tid == 0) {
        double r = red[0];
        for (int i = 1; i < nw; i++) r += red[i];
        red[0] = r;
    }
    __syncthreads();
    double r = red[0];
    __syncthreads();
    return r;
}

// ---------------- misc GEMM helpers ----------------
__device__ __forceinline__ uint32_t smem_u32(const void* p) {
    uint32_t a;
    asm("{ .reg .u64 t; cvta.to.shared.u64 t, %1; cvt.u32.u64 %0, t; }" : "=r"(a) : "l"(p));
    return a;
}
__device__ __forceinline__ void cp16(uint32_t dst, const void* src) {
    asm volatile("cp.async.cg.shared.global [%0], [%1], 16;" :: "r"(dst), "l"(src) : "memory");
}
#define CPCOMMIT()  asm volatile("cp.async.commit_group;" ::: "memory")
#define CPWAIT1()   asm volatile("cp.async.wait_group 1;" ::: "memory")
#define CPWAIT0()   asm volatile("cp.async.wait_group 0;" ::: "memory")
#define LDSM4(r, addr) \
    asm volatile("ldmatrix.sync.aligned.m8n8.x4.shared.b16 {%0,%1,%2,%3}, [%4];" \
        : "=r"((r)[0]), "=r"((r)[1]), "=r"((r)[2]), "=r"((r)[3]) : "r"(addr))
#define MMA8(c, a, b0, b1) \
    asm volatile("mma.sync.aligned.m16n8k32.row.col.s32.s8.s8.s32 " \
        "{%0,%1,%2,%3}, {%4,%5,%6,%7}, {%8,%9}, {%0,%1,%2,%3};" \
        : "+r"((c)[0]), "+r"((c)[1]), "+r"((c)[2]), "+r"((c)[3]) \
        : "r"((a)[0]), "r"((a)[1]), "r"((a)[2]), "r"((a)[3]), "r"(b0), "r"(b1))

// ---------------- precompute ----------------
__global__ void k_params(const float* __restrict__ log_decay, const float* __restrict__ u) {
    int i = threadIdx.x;
    float eld = expf(log_decay[i]);
    float wf  = expf(-eld);
    float lw  = logf(fmaxf(wf, 1e-38f));
    for (int n = 0; n <= 64; n++)
        g_wpow[n * 1024 + i] = expf(__fmul_rn((float)n, lw));
    g_ue[i] = expf(u[i]);
}

// ---------------- weight quantization ----------------
__global__ void k_wscale(const float* __restrict__ w) {
    __shared__ double red[8];
    const float* p = w + (size_t)blockIdx.x * Dn * Dn;
    double s = 0.0;
    for (int i = threadIdx.x; i < Dn * Dn; i += 256) s += (double)fabsf(p[i]);
    double tot = brD(s, red);
    if (threadIdx.x == 0)
        g_wscale[blockIdx.x] = fmaxf((float)(tot / (double)(Dn * Dn)), 1e-8f);
}

__global__ void k_wquant(const float* __restrict__ w) {
    int i = blockIdx.x * 256 + threadIdx.x;
    int m = i / (Dn * Dn);
    float s  = g_wscale[m];
    float vn = __fdiv_rn(w[i], s);
    vn = fminf(fmaxf(vn, -1.f), 1.f);
    ((signed char*)g_wq8)[i] = (signed char)(int)rintf(vn);
}

// ---------------- token shift + LN + act quant (int8 out) ----------------
__global__ void k_prep(const float* __restrict__ x,
                       const float* __restrict__ mu_r, const float* __restrict__ mu_k,
                       const float* __restrict__ mu_v, const float* __restrict__ mu_g,
                       const float* __restrict__ ln_g, const float* __restrict__ ln_b) {
    int row = blockIdx.x;
    int t   = row % Tn;
    int tid = threadIdx.x;
    __shared__ float sx[Dn], sdx[Dn];
    __shared__ double red[8];
    const float* mus[4] = {mu_r, mu_k, mu_v, mu_g};

    #pragma unroll
    for (int i = 0; i < 4; i++) {
        int d = tid + i * 256;
        float xv = x[(size_t)row * Dn + d];
        float xp = (t > 0) ? x[(size_t)(row - 1) * Dn + d] : 0.f;
        sx[d]  = xv;
        sdx[d] = __fsub_rn(xp, xv);
    }
    __syncthreads();

    for (int v = 0; v < 4; v++) {
        const float* mu = mus[v];
        float inp[4];
        double s = 0.0;
        #pragma unroll
        for (int i = 0; i < 4; i++) {
            int d = tid + i * 256;
            inp[i] = __fadd_rn(sx[d], __fmul_rn(sdx[d], mu[d]));
            s += (double)inp[i];
        }
        float mean = (float)(brD(s, red) * (1.0 / Dn));
        double s2 = 0.0;
        float dev[4];
        #pragma unroll
        for (int i = 0; i < 4; i++) {
            dev[i] = __fsub_rn(inp[i], mean);
            s2 += (double)__fmul_rn(dev[i], dev[i]);
        }
        float var  = (float)(brD(s2, red) * (1.0 / Dn));
        float rstd = (float)(1.0 / sqrt((double)__fadd_rn(var, 1e-5f)));
        float yv[4];
        double sa = 0.0;
        #pragma unroll
        for (int i = 0; i < 4; i++) {
            int d = tid + i * 256;
            float t1 = __fmul_rn(dev[i], rstd);
            float t2 = __fmul_rn(t1, ln_g[v * Dn + d]);
            yv[i] = __fadd_rn(t2, ln_b[v * Dn + d]);
            sa += (double)fabsf(yv[i]);
        }
        float meanabs = (float)(brD(sa, red) * (1.0 / Dn));
        float clipv = __fmul_rn(fmaxf(meanabs, 1e-8f), 2.5f);
        float scale = __fdiv_rn(clipv, 127.f);
        if (tid == 0) g_xscale[v][row] = scale;
        #pragma unroll
        for (int i = 0; i < 4; i++) {
            int d = tid + i * 256;
            float xs = __fdiv_rn(yv[i], scale);
            float xc = fminf(fmaxf(xs, -127.f), 127.f);
            ((signed char*)g_xq8[v])[(size_t)row * Dn + d] = (signed char)(int)rintf(xc);
        }
    }
}

// ---------------- int8 tensor-core GEMM via mma.sync (exact int32 accum) ----------------
#define ROWB 80
__global__ void __launch_bounds__(256, 2)
k_gemm_i8(const int4* __restrict__ A, const int4* __restrict__ W,
          const float* __restrict__ rowscale, const float* __restrict__ wsp,
          float* __restrict__ Cm) {
    __shared__ __align__(16) signed char As[2][128 * ROWB];
    __shared__ __align__(16) signed char Bs[2][128 * ROWB];
    int tid = threadIdx.x, lid = tid & 31, wid = tid >> 5;
    int m0 = blockIdx.y * 128, n0 = blockIdx.x * 128;
    int wm = (wid & 1) * 64, wn = (wid >> 1) * 32;

    int lrow = tid >> 1;
    int lc   = (tid & 1) * 2;
    const int4* Ag = A + (size_t)(m0 + lrow) * 64 + lc;
    const int4* Wg = W + (size_t)(n0 + lrow) * 64 + lc;
    uint32_t soff = (uint32_t)(lrow * ROWB + lc * 16);
    uint32_t sa[2] = {smem_u32(As[0]), smem_u32(As[1])};
    uint32_t sbm[2] = {smem_u32(Bs[0]), smem_u32(Bs[1])};

    int arow   = (lid & 7) + ((lid >> 3) & 1) * 8;
    int akhalf = lid >> 4;
    int brow   = (lid & 7) + (lid >> 4) * 8;
    int bkhalf = (lid >> 3) & 1;
    uint32_t aaddr[2][4], baddr[2][2];
    #pragma unroll
    for (int buf = 0; buf < 2; buf++) {
        #pragma unroll
        for (int mt = 0; mt < 4; mt++)
            aaddr[buf][mt] = sa[buf] + (uint32_t)((wm + mt * 16 + arow) * ROWB + akhalf * 16);
        #pragma unroll
        for (int bt = 0; bt < 2; bt++)
            baddr[buf][bt] = sbm[buf] + (uint32_t)((wn + bt * 16 + brow) * ROWB + bkhalf * 16);
    }

    int c[4][4][4];
    #pragma unroll
    for (int mt = 0; mt < 4; mt++)
        #pragma unroll
        for (int nt = 0; nt < 4; nt++)
            #pragma unroll
            for (int q = 0; q < 4; q++) c[mt][nt][q] = 0;

    cp16(sa[0] + soff,       Ag);
    cp16(sa[0] + soff + 16,  Ag + 1);
    cp16(sbm[0] + soff,      Wg);
    cp16(sbm[0] + soff + 16, Wg + 1);
    CPCOMMIT();

    for (int kb = 0; kb < 16; kb++) {
        int buf = kb & 1;
        if (kb < 15) {
            const int4* an = Ag + (kb + 1) * 4;
            const int4* wn_ = Wg + (kb + 1) * 4;
            int nb = buf ^ 1;
            cp16(sa[nb] + soff,       an);
            cp16(sa[nb] + soff + 16,  an + 1);
            cp16(sbm[nb] + soff,      wn_);
            cp16(sbm[nb] + soff + 16, wn_ + 1);
            CPCOMMIT();
            CPWAIT1();
        } else {
            CPWAIT0();
        }
        __syncthreads();

        #pragma unroll
        for (int ks = 0; ks < 2; ks++) {
            uint32_t af[4][4], bf[2][4];
            #pragma unroll
            for (int mt = 0; mt < 4; mt++) LDSM4(af[mt], aaddr[buf][mt] + ks * 32);
            #pragma unroll
            for (int bt = 0; bt < 2; bt++) LDSM4(bf[bt], baddr[buf][bt] + ks * 32);
            #pragma unroll
            for (int mt = 0; mt < 4; mt++)
                #pragma unroll
                for (int nt = 0; nt < 4; nt++)
                    MMA8(c[mt][nt], af[mt], bf[nt >> 1][(nt & 1) * 2], bf[nt >> 1][(nt & 1) * 2 + 1]);
        }
        __syncthreads();
    }

    float ws = *wsp;
    int g = lid >> 2, t4 = lid & 3;
    #pragma unroll
    for (int mt = 0; mt < 4; mt++) {
        int row = m0 + wm + mt * 16 + g;
        float rs0 = __fmul_rn(rowscale[row], ws);
        float rs1 = __fmul_rn(rowscale[row + 8], ws);
        float* cp0 = Cm + (size_t)row * Dn + n0 + wn;
        float* cp1 = cp0 + (size_t)8 * Dn;
        #pragma unroll
        for (int nt = 0; nt < 4; nt++) {
            int col = nt * 8 + t4 * 2;
            float2 v0, v1;
            v0.x = __fmul_rn((float)c[mt][nt][0], rs0);
            v0.y = __fmul_rn((float)c[mt][nt][1], rs0);
            v1.x = __fmul_rn((float)c[mt][nt][2], rs1);
            v1.y = __fmul_rn((float)c[mt][nt][3], rs1);
            *(float2*)(cp0 + col) = v0;
            *(float2*)(cp1 + col) = v1;
        }
    }
}

// ---------------- WKV: local (fwd decay-to-end) + intra (anti-causal) in one kernel ----------------
// 128 threads = 4 warps; warp w owns chunk blockIdx.x*4+w; lane owns o-pair (2*lane, 2*lane+1).
__global__ void __launch_bounds__(128, 2) k_wkv_kv() {
    int lane = threadIdx.x & 31, w = threadIdx.x >> 5;
    int idx = blockIdx.x * 4 + w;       // 0..2047
    int c = idx & 31, h = (idx >> 5) & 15, b = idx >> 9;
    __shared__ ulonglong2 kw[4][64];    // per-warp: {kk,kk | dd,dd} (or ww in intra)
    __shared__ u64 rs[4][64];           // per-warp: {rr,rr}

    size_t rb = (size_t)(b * Tn + c * 64) * Dn + h * 64;
    const float2* kf = (const float2*)(g_rkvg[1] + rb);
    const float2* rf = (const float2*)(g_rkvg[0] + rb);
    const u64*    vu = (const u64*)(g_rkvg[2] + rb);
    u64*          yu = (u64*)(g_y + rb);

    // ---- pass 1: local[s,o] = sum_t wpow[63-t][s]*k[t,s]*v[t,o] (accumulation, NOT recurrence)
    u64 ls[64];
    #pragma unroll
    for (int s = 0; s < 64; s++) ls[s] = 0ull;
    #pragma unroll 1
    for (int t = 0; t < 64; t++) {
        float2 kk = kf[t * 512 + lane];
        float2 dd = ((const float2*)(g_wpow + (63 - t) * 1024 + h * 64))[lane];
        kw[w][2 * lane]     = make_ulonglong2(pk(kk.x, kk.x), pk(dd.x, dd.x));
        kw[w][2 * lane + 1] = make_ulonglong2(pk(kk.y, kk.y), pk(dd.y, dd.y));
        __syncwarp();
        u64 v2 = vu[t * 512 + lane];
        #pragma unroll
        for (int s = 0; s < 64; s++) {
            ulonglong2 q = kw[w][s];
            u64 tmp; F2MUL(tmp, q.x, v2);
            F2FMA(ls[s], q.y, tmp, ls[s]);   // ls += dd * (k*v)   [FIXED operand order]
        }
        __syncwarp();
    }
    u64* lp = (u64*)(g_local + (size_t)idx * 4096);
    #pragma unroll
    for (int s = 0; s < 64; s++) lp[s * 32 + lane] = ls[s];

    // ---- pass 2: intra y_t[o] = sum_s r[t,s]*Q_t[s,o] + bonus_t*v[t,o], Q_t = kv_t + w*Q_{t+1}
    float2 wwv = ((const float2*)(g_wpow + 1024 + h * 64))[lane];
    float2 uev = ((const float2*)(g_ue + h * 64))[lane];
    kw[w][2 * lane].y     = pk(wwv.x, wwv.x);
    kw[w][2 * lane + 1].y = pk(wwv.y, wwv.y);
    u64 Q[64];
    #pragma unroll
    for (int s = 0; s < 64; s++) Q[s] = 0ull;
    #pragma unroll 1
    for (int t = 63; t >= 0; t--) {
        float2 kk = kf[t * 512 + lane];
        float2 rr = rf[t * 512 + lane];
        kw[w][2 * lane].x     = pk(kk.x, kk.x);
        kw[w][2 * lane + 1].x = pk(kk.y, kk.y);
        rs[w][2 * lane]       = pk(rr.x, rr.x);
        rs[w][2 * lane + 1]   = pk(rr.y, rr.y);
        // bonus_t = sum_s r*ue*k  (o-independent)
        float p = __fadd_rn(__fmul_rn(__fmul_rn(rr.x, uev.x), kk.x),
                            __fmul_rn(__fmul_rn(rr.y, uev.y), kk.y));
        #pragma unroll
        for (int o = 16; o; o >>= 1) p += __shfl_xor_sync(0xffffffffu, p, o);
        __syncwarp();
        u64 v2 = vu[t * 512 + lane];
        u64 y2; F2MUL(y2, pk(p, p), v2);
        #pragma unroll
        for (int s = 0; s < 64; s++) {
            ulonglong2 q = kw[w][s];
            u64 tmp; F2MUL(tmp, q.x, v2);
            F2FMA(Q[s], q.y, Q[s], tmp);       // Q = w*Q + kv  (true recurrence)
            F2FMA(y2, rs[w][s], Q[s], y2);     // y += r*Q
        }
        yu[t * 512 + lane] = y2;
        __syncwarp();
    }
}

// ---------------- WKV scan over chunks ----------------
__global__ void k_wkv_scan() {
    int bh = blockIdx.x;
    int h  = bh & 15;
    int tid = threadIdx.x;
    float cur[16], wc[16];
    #pragma unroll
    for (int j = 0; j < 16; j++) {
        cur[j] = 0.f;
        int e = tid + j * 256;
        wc[j] = g_wpow[64 * 1024 + h * 64 + (e >> 6)];
    }
    for (int c = 0; c < NC; c++) {
        size_t base = ((size_t)bh * NC + c) * 4096;
        #pragma unroll
        for (int j = 0; j < 16; j++) {
            int e = tid + j * 256;
            g_init[base + e] = cur[j];
            cur[j] = __fadd_rn(__fmul_rn(wc[j], cur[j]), g_local[base + e]);
        }
    }
}

// ---------------- WKV state term: y += (r .* wpow[t+1]) @ S0 ----------------
__global__ void __launch_bounds__(128, 2) k_wkv_state() {
    int lane = threadIdx.x & 31, w = threadIdx.x >> 5;
    int idx = blockIdx.x * 4 + w;
    int c = idx & 31, h = (idx >> 5) & 15, b = idx >> 9;
    __shared__ u64 rp[4][64];

    size_t rb = (size_t)(b * Tn + c * 64) * Dn + h * 64;
    const float2* rf = (const float2*)(g_rkvg[0] + rb);
    u64* yu = (u64*)(g_y + rb);
    const u64* s0 = (const u64*)(g_init + (size_t)idx * 4096);

    u64 S[64];
    #pragma unroll
    for (int s = 0; s < 64; s++) S[s] = s0[s * 32 + lane];

    #pragma unroll 1
    for (int t = 0; t < 64; t++) {
        float2 rr = rf[t * 512 + lane];
        float2 cw = ((const float2*)(g_wpow + (t + 1) * 1024 + h * 64))[lane];
        float rx = __fmul_rn(rr.x, cw.x);
        float ry = __fmul_rn(rr.y, cw.y);
        rp[w][2 * lane]     = pk(rx, rx);
        rp[w][2 * lane + 1] = pk(ry, ry);
        __syncwarp();
        u64 y2 = yu[t * 512 + lane];
        #pragma unroll
        for (int s = 0; s < 64; s++)
            F2FMA(y2, rp[w][s], S[s], y2);
        yu[t * 512 + lane] = y2;
        __syncwarp();
    }
}

// ---------------- GroupNorm + SiLU + LN(4) + act quant (int8 out) ----------------
__global__ void k_gn(const float* __restrict__ gn_g, const float* __restrict__ gn_b,
                     const float* __restrict__ ln_g, const float* __restrict__ ln_b) {
    int row = blockIdx.x;
    int tid = threadIdx.x;
    __shared__ float sz[Dn];
    __shared__ double red[8];

    int head = tid >> 4, sub = tid & 15;
    float yv[4];
    size_t hb = (size_t)row * Dn + head * 64 + sub;
    #pragma unroll
    for (int i = 0; i < 4; i++) yv[i] = g_y[hb + 16 * i];
    double s = (double)yv[0] + (double)yv[1] + (double)yv[2] + (double)yv[3];
    #pragma unroll
    for (int off = 8; off > 0; off >>= 1) s += __shfl_xor_sync(0xffffffffu, s, off, 16);
    float mean = (float)(s * (1.0 / 64.0));
    double s2 = 0.0;
    float dev[4];
    #pragma unroll
    for (int i = 0; i < 4; i++) {
        dev[i] = __fsub_rn(yv[i], mean);
        s2 += (double)__fmul_rn(dev[i], dev[i]);
    }
    #pragma unroll
    for (int off = 8; off > 0; off >>= 1) s2 += __shfl_xor_sync(0xffffffffu, s2, off, 16);
    float var  = (float)(s2 * (1.0 / 64.0));
    float rstd = (float)(1.0 / sqrt((double)__fadd_rn(var, 1e-5f)));
    #pragma unroll
    for (int i = 0; i < 4; i++) {
        int d = head * 64 + sub + 16 * i;
        float yn = __fmul_rn(dev[i], rstd);
        float yg = __fadd_rn(__fmul_rn(yn, gn_g[d]), gn_b[d]);
        float gv = g_rkvg[3][(size_t)row * Dn + d];
        float sig = __fdiv_rn(1.f, __fadd_rn(1.f, expf(-gv)));
        float sil = __fmul_rn(gv, sig);
        sz[d] = __fmul_rn(yg, sil);
    }
    __syncthreads();

    float inp[4];
    double ssum = 0.0;
    #pragma unroll
    for (int i = 0; i < 4; i++) { int d = tid + i * 256; inp[i] = sz[d]; ssum += (double)inp[i]; }
    float m2 = (float)(brD(ssum, red) * (1.0 / Dn));
    double sv = 0.0;
    float dv[4];
    #pragma unroll
    for (int i = 0; i < 4; i++) {
        dv[i] = __fsub_rn(inp[i], m2);
        sv += (double)__fmul_rn(dv[i], dv[i]);
    }
    float var2 = (float)(brD(sv, red) * (1.0 / Dn));
    float rst2 = (float)(1.0 / sqrt((double)__fadd_rn(var2, 1e-5f)));
    float yln[4];
    double sa = 0.0;
    #pragma unroll
    for (int i = 0; i < 4; i++) {
        int d = tid + i * 256;
        float t1 = __fmul_rn(dv[i], rst2);
        float t2 = __fmul_rn(t1, ln_g[4 * Dn + d]);
        yln[i] = __fadd_rn(t2, ln_b[4 * Dn + d]);
        sa += (double)fabsf(yln[i]);
    }
    float meanabs = (float)(brD(sa, red) * (1.0 / Dn));
    float clipv = __fmul_rn(fmaxf(meanabs, 1e-8f), 2.5f);
    float scale = __fdiv_rn(clipv, 127.f);
    if (tid == 0) g_zscale[row] = scale;
    #pragma unroll
    for (int i = 0; i < 4; i++) {
        int d = tid + i * 256;
        float xs = __fdiv_rn(yln[i], scale);
        float xc = fminf(fmaxf(xs, -127.f), 127.f);
        ((signed char*)g_zq8)[(size_t)row * Dn + d] = (signed char)(int)rintf(xc);
    }
}

// ---------------- launch ----------------
extern "C" void kernel_launch(void* const* d_in, const int* in_sizes, int n_in,
                              void* d_out, int out_size) {
    const float* x         = (const float*)d_in[0];
    const float* mu_r      = (const float*)d_in[1];
    const float* mu_k      = (const float*)d_in[2];
    const float* mu_v      = (const float*)d_in[3];
    const float* mu_g      = (const float*)d_in[4];
    const float* log_decay = (const float*)d_in[5];
    const float* u         = (const float*)d_in[6];
    const float* proj_w    = (const float*)d_in[7];
    const float* ln_g      = (const float*)d_in[8];
    const float* ln_b      = (const float*)d_in[9];
    const float* gn_g      = (const float*)d_in[10];
    const float* gn_b      = (const float*)d_in[11];

    int4 *xq8, *wq8, *zq8;
    float *rkvg, *xscale, *zscale, *wscale;
    cudaGetSymbolAddress((void**)&xq8,    g_xq8);
    cudaGetSymbolAddress((void**)&wq8,    g_wq8);
    cudaGetSymbolAddress((void**)&zq8,    g_zq8);
    cudaGetSymbolAddress((void**)&rkvg,   g_rkvg);
    cudaGetSymbolAddress((void**)&xscale, g_xscale);
    cudaGetSymbolAddress((void**)&zscale, g_zscale);
    cudaGetSymbolAddress((void**)&wscale, g_wscale);

    k_params<<<1, 1024>>>(log_decay, u);
    k_wscale<<<5, 256>>>(proj_w);
    k_wquant<<<5 * Dn * Dn / 256, 256>>>(proj_w);
    k_prep<<<BT, 256>>>(x, mu_r, mu_k, mu_v, mu_g, ln_g, ln_b);

    dim3 ggrid(Dn / 128, BT / 128);
    for (int v = 0; v < 4; v++)
        k_gemm_i8<<<ggrid, 256>>>(xq8 + (size_t)v * (BT * Dn / 16),
                                  wq8 + (size_t)v * (Dn * Dn / 16),
                                  xscale + (size_t)v * BT,
                                  wscale + v,
                                  rkvg + (size_t)v * BT * Dn);

    k_wkv_kv<<<Bn * Hn * NC / 4, 128>>>();
    k_wkv_scan<<<Bn * Hn, 256>>>();
    k_wkv_state<<<Bn * Hn * NC / 4, 128>>>();

    k_gn<<<BT, 256>>>(gn_g, gn_b, ln_g, ln_b);

    k_gemm_i8<<<ggrid, 256>>>(zq8, wq8 + (size_t)4 * (Dn * Dn / 16),
                              zscale, wscale + 4, (float*)d_out);
}

// round 14
// speedup vs baseline: 1.9522x; 1.2584x over previous
#include <cuda_runtime.h>
#include <math.h>
#include <stdint.h>

// Problem constants
#define Bn 4
#define Tn 2048
#define Dn 1024
#define Hn 16
#define Sn 64
#define NC 32
#define BT (Bn*Tn)   // 8192 rows

typedef unsigned long long u64;

// ---------------- scratch ----------------
__device__ int4  g_xq8[4][BT*Dn/16];
__device__ float g_xscale[4][BT];
__device__ int4  g_wq8[5][Dn*Dn/16];
__device__ float g_wscale[5];
__device__ int4  g_zq8[BT*Dn/16];
__device__ float g_zscale[BT];
__device__ float g_rkvg[4][BT*Dn];
__device__ float g_y[BT*Dn];
__device__ float g_local[Bn*Hn*NC*Sn*Sn];
__device__ float g_init [Bn*Hn*NC*Sn*Sn];
__device__ float g_wpow[65*1024];
__device__ float g_ue[Hn*Sn];

// ---------------- f32x2 packed helpers ----------------
#define F2MUL(d, a, b)    asm("mul.rn.f32x2 %0, %1, %2;" : "=l"(d) : "l"(a), "l"(b))
#define F2FMA(d, a, b, c) asm("fma.rn.f32x2 %0, %1, %2, %3;" : "=l"(d) : "l"(a), "l"(b), "l"(c))
__device__ __forceinline__ u64 pk(float x, float y) {
    u64 r; asm("mov.b64 %0, {%1, %2};" : "=l"(r) : "f"(x), "f"(y)); return r;
}

// ---------------- warp reduce (fp64, no barriers) ----------------
__device__ __forceinline__ double wrD(double v) {
    #pragma unroll
    for (int o = 16; o; o >>= 1) v += __shfl_xor_sync(0xffffffffu, v, o);
    return v;
}

// block reduce for k_wscale only
__device__ __forceinline__ double brD(double v, double* red) {
    int tid = threadIdx.x, lane = tid & 31, wid = tid >> 5;
    int nw = blockDim.x >> 5;
    v = wrD(v);
    if (lane == 0) red[wid] = v;
    __syncthreads();
    if (tid == 0) {
        double r = red[0];
        for (int i = 1; i < nw; i++) r += red[i];
        red[0] = r;
    }
    __syncthreads();
    double r = red[0];
    __syncthreads();
    return r;
}

// ---------------- misc GEMM helpers ----------------
__device__ __forceinline__ uint32_t smem_u32(const void* p) {
    uint32_t a;
    asm("{ .reg .u64 t; cvta.to.shared.u64 t, %1; cvt.u32.u64 %0, t; }" : "=r"(a) : "l"(p));
    return a;
}
__device__ __forceinline__ void cp16(uint32_t dst, const void* src) {
    asm volatile("cp.async.cg.shared.global [%0], [%1], 16;" :: "r"(dst), "l"(src) : "memory");
}
#define CPCOMMIT()  asm volatile("cp.async.commit_group;" ::: "memory")
#define CPWAIT1()   asm volatile("cp.async.wait_group 1;" ::: "memory")
#define CPWAIT0()   asm volatile("cp.async.wait_group 0;" ::: "memory")
#define LDSM4(r, addr) \
    asm volatile("ldmatrix.sync.aligned.m8n8.x4.shared.b16 {%0,%1,%2,%3}, [%4];" \
        : "=r"((r)[0]), "=r"((r)[1]), "=r"((r)[2]), "=r"((r)[3]) : "r"(addr))
#define MMA8(c, a, b0, b1) \
    asm volatile("mma.sync.aligned.m16n8k32.row.col.s32.s8.s8.s32 " \
        "{%0,%1,%2,%3}, {%4,%5,%6,%7}, {%8,%9}, {%0,%1,%2,%3};" \
        : "+r"((c)[0]), "+r"((c)[1]), "+r"((c)[2]), "+r"((c)[3]) \
        : "r"((a)[0]), "r"((a)[1]), "r"((a)[2]), "r"((a)[3]), "r"(b0), "r"(b1))

// ---------------- precompute ----------------
__global__ void k_params(const float* __restrict__ log_decay, const float* __restrict__ u) {
    int i = threadIdx.x;
    float eld = expf(log_decay[i]);
    float wf  = expf(-eld);
    float lw  = logf(fmaxf(wf, 1e-38f));
    for (int n = 0; n <= 64; n++)
        g_wpow[n * 1024 + i] = expf(__fmul_rn((float)n, lw));
    g_ue[i] = expf(u[i]);
}

// ---------------- weight quantization ----------------
__global__ void k_wscale(const float* __restrict__ w) {
    __shared__ double red[8];
    const float* p = w + (size_t)blockIdx.x * Dn * Dn;
    double s = 0.0;
    for (int i = threadIdx.x; i < Dn * Dn; i += 256) s += (double)fabsf(p[i]);
    double tot = brD(s, red);
    if (threadIdx.x == 0)
        g_wscale[blockIdx.x] = fmaxf((float)(tot / (double)(Dn * Dn)), 1e-8f);
}

__global__ void k_wquant(const float* __restrict__ w) {
    int i = blockIdx.x * 256 + threadIdx.x;
    int m = i / (Dn * Dn);
    float s  = g_wscale[m];
    float vn = __fdiv_rn(w[i], s);
    vn = fminf(fmaxf(vn, -1.f), 1.f);
    ((signed char*)g_wq8)[i] = (signed char)(int)rintf(vn);
}

// ---------------- int8 pack+store: 32 consecutive bytes per lane ----------------
__device__ __forceinline__ void store_q32(signed char* base, const float* yv, float scale) {
    int w[8];
    #pragma unroll
    for (int j = 0; j < 8; j++) {
        int q0 = (int)rintf(fminf(fmaxf(__fdiv_rn(yv[4*j+0], scale), -127.f), 127.f));
        int q1 = (int)rintf(fminf(fmaxf(__fdiv_rn(yv[4*j+1], scale), -127.f), 127.f));
        int q2 = (int)rintf(fminf(fmaxf(__fdiv_rn(yv[4*j+2], scale), -127.f), 127.f));
        int q3 = (int)rintf(fminf(fmaxf(__fdiv_rn(yv[4*j+3], scale), -127.f), 127.f));
        w[j] = (q0 & 0xff) | ((q1 & 0xff) << 8) | ((q2 & 0xff) << 16) | ((q3 & 0xff) << 24);
    }
    ((int4*)base)[0] = make_int4(w[0], w[1], w[2], w[3]);
    ((int4*)base)[1] = make_int4(w[4], w[5], w[6], w[7]);
}

// ---------------- token shift + LN + act quant: ONE WARP PER ROW, no barriers ----------------
__global__ void __launch_bounds__(256)
k_prep(const float* __restrict__ x,
       const float* __restrict__ mu_r, const float* __restrict__ mu_k,
       const float* __restrict__ mu_v, const float* __restrict__ mu_g,
       const float* __restrict__ ln_g, const float* __restrict__ ln_b) {
    int row  = blockIdx.x * 8 + (threadIdx.x >> 5);
    int lane = threadIdx.x & 31;
    int t    = row % Tn;

    // lane owns d = lane*32 .. lane*32+31
    const float4* xr = (const float4*)(x + (size_t)row * Dn) + lane * 8;
    const float4* xp = (const float4*)(x + (size_t)(row - 1) * Dn) + lane * 8;

    float xv[32], dx[32];
    #pragma unroll
    for (int j = 0; j < 8; j++) {
        float4 a = xr[j];
        float4 p = (t > 0) ? xp[j] : make_float4(0.f, 0.f, 0.f, 0.f);
        xv[4*j+0] = a.x; xv[4*j+1] = a.y; xv[4*j+2] = a.z; xv[4*j+3] = a.w;
        dx[4*j+0] = __fsub_rn(p.x, a.x); dx[4*j+1] = __fsub_rn(p.y, a.y);
        dx[4*j+2] = __fsub_rn(p.z, a.z); dx[4*j+3] = __fsub_rn(p.w, a.w);
    }

    #pragma unroll 1
    for (int v = 0; v < 4; v++) {
        const float* mu = (v == 0) ? mu_r : (v == 1) ? mu_k : (v == 2) ? mu_v : mu_g;
        const float4* muv = (const float4*)mu + lane * 8;
        float inp[32];
        double s = 0.0;
        #pragma unroll
        for (int j = 0; j < 8; j++) {
            float4 m = muv[j];
            float mm[4] = {m.x, m.y, m.z, m.w};
            #pragma unroll
            for (int q = 0; q < 4; q++) {
                int i = 4*j + q;
                inp[i] = __fadd_rn(xv[i], __fmul_rn(dx[i], mm[q]));
                s += (double)inp[i];
            }
        }
        float mean = (float)(wrD(s) * (1.0 / Dn));
        double s2 = 0.0;
        #pragma unroll
        for (int i = 0; i < 32; i++) {
            float d = __fsub_rn(inp[i], mean);
            inp[i] = d;                      // inp now holds dev
            s2 += (double)__fmul_rn(d, d);
        }
        float var  = (float)(wrD(s2) * (1.0 / Dn));
        float rstd = (float)(1.0 / sqrt((double)__fadd_rn(var, 1e-5f)));

        const float4* gp = (const float4*)(ln_g + v * Dn) + lane * 8;
        const float4* bp = (const float4*)(ln_b + v * Dn) + lane * 8;
        double sa = 0.0;
        #pragma unroll
        for (int j = 0; j < 8; j++) {
            float4 gg = gp[j], bb = bp[j];
            float ga[4] = {gg.x, gg.y, gg.z, gg.w};
            float ba[4] = {bb.x, bb.y, bb.z, bb.w};
            #pragma unroll
            for (int q = 0; q < 4; q++) {
                int i = 4*j + q;
                float t1 = __fmul_rn(inp[i], rstd);
                float yv2 = __fadd_rn(__fmul_rn(t1, ga[q]), ba[q]);
                inp[i] = yv2;                // inp now holds yv
                sa += (double)fabsf(yv2);
            }
        }
        float meanabs = (float)(wrD(sa) * (1.0 / Dn));
        float clipv = __fmul_rn(fmaxf(meanabs, 1e-8f), 2.5f);
        float scale = __fdiv_rn(clipv, 127.f);
        if (lane == 0) g_xscale[v][row] = scale;
        store_q32((signed char*)g_xq8[v] + (size_t)row * Dn + lane * 32, inp, scale);
    }
}

// ---------------- int8 tensor-core GEMM via mma.sync (exact int32 accum) ----------------
#define ROWB 80
__global__ void __launch_bounds__(256, 2)
k_gemm_i8(const int4* __restrict__ A, const int4* __restrict__ W,
          const float* __restrict__ rowscale, const float* __restrict__ wsp,
          float* __restrict__ Cm) {
    __shared__ __align__(16) signed char As[2][128 * ROWB];
    __shared__ __align__(16) signed char Bs[2][128 * ROWB];
    int tid = threadIdx.x, lid = tid & 31, wid = tid >> 5;
    int m0 = blockIdx.y * 128, n0 = blockIdx.x * 128;
    int wm = (wid & 1) * 64, wn = (wid >> 1) * 32;

    int lrow = tid >> 1;
    int lc   = (tid & 1) * 2;
    const int4* Ag = A + (size_t)(m0 + lrow) * 64 + lc;
    const int4* Wg = W + (size_t)(n0 + lrow) * 64 + lc;
    uint32_t soff = (uint32_t)(lrow * ROWB + lc * 16);
    uint32_t sa[2] = {smem_u32(As[0]), smem_u32(As[1])};
    uint32_t sbm[2] = {smem_u32(Bs[0]), smem_u32(Bs[1])};

    int arow   = (lid & 7) + ((lid >> 3) & 1) * 8;
    int akhalf = lid >> 4;
    int brow   = (lid & 7) + (lid >> 4) * 8;
    int bkhalf = (lid >> 3) & 1;
    uint32_t aaddr[2][4], baddr[2][2];
    #pragma unroll
    for (int buf = 0; buf < 2; buf++) {
        #pragma unroll
        for (int mt = 0; mt < 4; mt++)
            aaddr[buf][mt] = sa[buf] + (uint32_t)((wm + mt * 16 + arow) * ROWB + akhalf * 16);
        #pragma unroll
        for (int bt = 0; bt < 2; bt++)
            baddr[buf][bt] = sbm[buf] + (uint32_t)((wn + bt * 16 + brow) * ROWB + bkhalf * 16);
    }

    int c[4][4][4];
    #pragma unroll
    for (int mt = 0; mt < 4; mt++)
        #pragma unroll
        for (int nt = 0; nt < 4; nt++)
            #pragma unroll
            for (int q = 0; q < 4; q++) c[mt][nt][q] = 0;

    cp16(sa[0] + soff,       Ag);
    cp16(sa[0] + soff + 16,  Ag + 1);
    cp16(sbm[0] + soff,      Wg);
    cp16(sbm[0] + soff + 16, Wg + 1);
    CPCOMMIT();

    for (int kb = 0; kb < 16; kb++) {
        int buf = kb & 1;
        if (kb < 15) {
            const int4* an = Ag + (kb + 1) * 4;
            const int4* wn_ = Wg + (kb + 1) * 4;
            int nb = buf ^ 1;
            cp16(sa[nb] + soff,       an);
            cp16(sa[nb] + soff + 16,  an + 1);
            cp16(sbm[nb] + soff,      wn_);
            cp16(sbm[nb] + soff + 16, wn_ + 1);
            CPCOMMIT();
            CPWAIT1();
        } else {
            CPWAIT0();
        }
        __syncthreads();

        #pragma unroll
        for (int ks = 0; ks < 2; ks++) {
            uint32_t af[4][4], bf[2][4];
            #pragma unroll
            for (int mt = 0; mt < 4; mt++) LDSM4(af[mt], aaddr[buf][mt] + ks * 32);
            #pragma unroll
            for (int bt = 0; bt < 2; bt++) LDSM4(bf[bt], baddr[buf][bt] + ks * 32);
            #pragma unroll
            for (int mt = 0; mt < 4; mt++)
                #pragma unroll
                for (int nt = 0; nt < 4; nt++)
                    MMA8(c[mt][nt], af[mt], bf[nt >> 1][(nt & 1) * 2], bf[nt >> 1][(nt & 1) * 2 + 1]);
        }
        __syncthreads();
    }

    float ws = *wsp;
    int g = lid >> 2, t4 = lid & 3;
    #pragma unroll
    for (int mt = 0; mt < 4; mt++) {
        int row = m0 + wm + mt * 16 + g;
        float rs0 = __fmul_rn(rowscale[row], ws);
        float rs1 = __fmul_rn(rowscale[row + 8], ws);
        float* cp0 = Cm + (size_t)row * Dn + n0 + wn;
        float* cp1 = cp0 + (size_t)8 * Dn;
        #pragma unroll
        for (int nt = 0; nt < 4; nt++) {
            int col = nt * 8 + t4 * 2;
            float2 v0, v1;
            v0.x = __fmul_rn((float)c[mt][nt][0], rs0);
            v0.y = __fmul_rn((float)c[mt][nt][1], rs0);
            v1.x = __fmul_rn((float)c[mt][nt][2], rs1);
            v1.y = __fmul_rn((float)c[mt][nt][3], rs1);
            *(float2*)(cp0 + col) = v0;
            *(float2*)(cp1 + col) = v1;
        }
    }
}

// ---------------- WKV: local + intra (unchanged from passing R13) ----------------
__global__ void __launch_bounds__(128, 2) k_wkv_kv() {
    int lane = threadIdx.x & 31, w = threadIdx.x >> 5;
    int idx = blockIdx.x * 4 + w;
    int c = idx & 31, h = (idx >> 5) & 15, b = idx >> 9;
    __shared__ ulonglong2 kw[4][64];
    __shared__ u64 rs[4][64];

    size_t rb = (size_t)(b * Tn + c * 64) * Dn + h * 64;
    const float2* kf = (const float2*)(g_rkvg[1] + rb);
    const float2* rf = (const float2*)(g_rkvg[0] + rb);
    const u64*    vu = (const u64*)(g_rkvg[2] + rb);
    u64*          yu = (u64*)(g_y + rb);

    u64 ls[64];
    #pragma unroll
    for (int s = 0; s < 64; s++) ls[s] = 0ull;
    #pragma unroll 1
    for (int t = 0; t < 64; t++) {
        float2 kk = kf[t * 512 + lane];
        float2 dd = ((const float2*)(g_wpow + (63 - t) * 1024 + h * 64))[lane];
        kw[w][2 * lane]     = make_ulonglong2(pk(kk.x, kk.x), pk(dd.x, dd.x));
        kw[w][2 * lane + 1] = make_ulonglong2(pk(kk.y, kk.y), pk(dd.y, dd.y));
        __syncwarp();
        u64 v2 = vu[t * 512 + lane];
        #pragma unroll
        for (int s = 0; s < 64; s++) {
            ulonglong2 q = kw[w][s];
            u64 tmp; F2MUL(tmp, q.x, v2);
            F2FMA(ls[s], q.y, tmp, ls[s]);   // ls += dd * (k*v)
        }
        __syncwarp();
    }
    u64* lp = (u64*)(g_local + (size_t)idx * 4096);
    #pragma unroll
    for (int s = 0; s < 64; s++) lp[s * 32 + lane] = ls[s];

    float2 wwv = ((const float2*)(g_wpow + 1024 + h * 64))[lane];
    float2 uev = ((const float2*)(g_ue + h * 64))[lane];
    kw[w][2 * lane].y     = pk(wwv.x, wwv.x);
    kw[w][2 * lane + 1].y = pk(wwv.y, wwv.y);
    u64 Q[64];
    #pragma unroll
    for (int s = 0; s < 64; s++) Q[s] = 0ull;
    #pragma unroll 1
    for (int t = 63; t >= 0; t--) {
        float2 kk = kf[t * 512 + lane];
        float2 rr = rf[t * 512 + lane];
        kw[w][2 * lane].x     = pk(kk.x, kk.x);
        kw[w][2 * lane + 1].x = pk(kk.y, kk.y);
        rs[w][2 * lane]       = pk(rr.x, rr.x);
        rs[w][2 * lane + 1]   = pk(rr.y, rr.y);
        float p = __fadd_rn(__fmul_rn(__fmul_rn(rr.x, uev.x), kk.x),
                            __fmul_rn(__fmul_rn(rr.y, uev.y), kk.y));
        #pragma unroll
        for (int o = 16; o; o >>= 1) p += __shfl_xor_sync(0xffffffffu, p, o);
        __syncwarp();
        u64 v2 = vu[t * 512 + lane];
        u64 y2; F2MUL(y2, pk(p, p), v2);
        #pragma unroll
        for (int s = 0; s < 64; s++) {
            ulonglong2 q = kw[w][s];
            u64 tmp; F2MUL(tmp, q.x, v2);
            F2FMA(Q[s], q.y, Q[s], tmp);
            F2FMA(y2, rs[w][s], Q[s], y2);
        }
        yu[t * 512 + lane] = y2;
        __syncwarp();
    }
}

// ---------------- WKV scan over chunks ----------------
__global__ void k_wkv_scan() {
    int bh = blockIdx.x;
    int h  = bh & 15;
    int tid = threadIdx.x;
    float cur[16], wc[16];
    #pragma unroll
    for (int j = 0; j < 16; j++) {
        cur[j] = 0.f;
        int e = tid + j * 256;
        wc[j] = g_wpow[64 * 1024 + h * 64 + (e >> 6)];
    }
    for (int c = 0; c < NC; c++) {
        size_t base = ((size_t)bh * NC + c) * 4096;
        #pragma unroll
        for (int j = 0; j < 16; j++) {
            int e = tid + j * 256;
            g_init[base + e] = cur[j];
            cur[j] = __fadd_rn(__fmul_rn(wc[j], cur[j]), g_local[base + e]);
        }
    }
}

// ---------------- WKV state term ----------------
__global__ void __launch_bounds__(128, 2) k_wkv_state() {
    int lane = threadIdx.x & 31, w = threadIdx.x >> 5;
    int idx = blockIdx.x * 4 + w;
    int c = idx & 31, h = (idx >> 5) & 15, b = idx >> 9;
    __shared__ u64 rp[4][64];

    size_t rb = (size_t)(b * Tn + c * 64) * Dn + h * 64;
    const float2* rf = (const float2*)(g_rkvg[0] + rb);
    u64* yu = (u64*)(g_y + rb);
    const u64* s0 = (const u64*)(g_init + (size_t)idx * 4096);

    u64 S[64];
    #pragma unroll
    for (int s = 0; s < 64; s++) S[s] = s0[s * 32 + lane];

    #pragma unroll 1
    for (int t = 0; t < 64; t++) {
        float2 rr = rf[t * 512 + lane];
        float2 cw = ((const float2*)(g_wpow + (t + 1) * 1024 + h * 64))[lane];
        float rx = __fmul_rn(rr.x, cw.x);
        float ry = __fmul_rn(rr.y, cw.y);
        rp[w][2 * lane]     = pk(rx, rx);
        rp[w][2 * lane + 1] = pk(ry, ry);
        __syncwarp();
        u64 y2 = yu[t * 512 + lane];
        #pragma unroll
        for (int s = 0; s < 64; s++)
            F2FMA(y2, rp[w][s], S[s], y2);
        yu[t * 512 + lane] = y2;
        __syncwarp();
    }
}

// ---------------- GroupNorm + SiLU + LN(4) + quant: ONE WARP PER ROW ----------------
__global__ void __launch_bounds__(256)
k_gn(const float* __restrict__ gn_g, const float* __restrict__ gn_b,
     const float* __restrict__ ln_g, const float* __restrict__ ln_b) {
    int row  = blockIdx.x * 8 + (threadIdx.x >> 5);
    int lane = threadIdx.x & 31;

    // lane owns d = lane*32 .. +31  (head = lane>>1; partner lane^1 completes the 64-ch group)
    float yv[32];
    const float4* yr = (const float4*)(g_y + (size_t)row * Dn) + lane * 8;
    #pragma unroll
    for (int j = 0; j < 8; j++) {
        float4 a = yr[j];
        yv[4*j+0] = a.x; yv[4*j+1] = a.y; yv[4*j+2] = a.z; yv[4*j+3] = a.w;
    }

    // GroupNorm over 64 channels = this lane + partner
    double gs = 0.0;
    #pragma unroll
    for (int i = 0; i < 32; i++) gs += (double)yv[i];
    gs += __shfl_xor_sync(0xffffffffu, gs, 1);
    float mean = (float)(gs * (1.0 / 64.0));
    double s2 = 0.0;
    #pragma unroll
    for (int i = 0; i < 32; i++) {
        float d = __fsub_rn(yv[i], mean);
        yv[i] = d;                           // dev
        s2 += (double)__fmul_rn(d, d);
    }
    s2 += __shfl_xor_sync(0xffffffffu, s2, 1);
    float var  = (float)(s2 * (1.0 / 64.0));
    float rstd = (float)(1.0 / sqrt((double)__fadd_rn(var, 1e-5f)));

    const float4* ggp = (const float4*)gn_g + lane * 8;
    const float4* gbp = (const float4*)gn_b + lane * 8;
    const float4* gvp = (const float4*)(g_rkvg[3] + (size_t)row * Dn) + lane * 8;
    double ssum = 0.0;
    #pragma unroll
    for (int j = 0; j < 8; j++) {
        float4 gg = ggp[j], bb = gbp[j], gv4 = gvp[j];
        float ga[4] = {gg.x, gg.y, gg.z, gg.w};
        float ba[4] = {bb.x, bb.y, bb.z, bb.w};
        float gv[4] = {gv4.x, gv4.y, gv4.z, gv4.w};
        #pragma unroll
        for (int q = 0; q < 4; q++) {
            int i = 4*j + q;
            float yn = __fmul_rn(yv[i], rstd);
            float yg = __fadd_rn(__fmul_rn(yn, ga[q]), ba[q]);
            float sig = __fdiv_rn(1.f, __fadd_rn(1.f, expf(-gv[q])));
            float sil = __fmul_rn(gv[q], sig);
            yv[i] = __fmul_rn(yg, sil);      // gated value
            ssum += (double)yv[i];
        }
    }

    // LayerNorm over full row (warp-wide)
    float m2 = (float)(wrD(ssum) * (1.0 / Dn));
    double sv = 0.0;
    #pragma unroll
    for (int i = 0; i < 32; i++) {
        float d = __fsub_rn(yv[i], m2);
        yv[i] = d;
        sv += (double)__fmul_rn(d, d);
    }
    float var2 = (float)(wrD(sv) * (1.0 / Dn));
    float rst2 = (float)(1.0 / sqrt((double)__fadd_rn(var2, 1e-5f)));

    const float4* lgp = (const float4*)(ln_g + 4 * Dn) + lane * 8;
    const float4* lbp = (const float4*)(ln_b + 4 * Dn) + lane * 8;
    double sa = 0.0;
    #pragma unroll
    for (int j = 0; j < 8; j++) {
        float4 gg = lgp[j], bb = lbp[j];
        float ga[4] = {gg.x, gg.y, gg.z, gg.w};
        float ba[4] = {bb.x, bb.y, bb.z, bb.w};
        #pragma unroll
        for (int q = 0; q < 4; q++) {
            int i = 4*j + q;
            float t1 = __fmul_rn(yv[i], rst2);
            float y2 = __fadd_rn(__fmul_rn(t1, ga[q]), ba[q]);
            yv[i] = y2;
            sa += (double)fabsf(y2);
        }
    }
    float meanabs = (float)(wrD(sa) * (1.0 / Dn));
    float clipv = __fmul_rn(fmaxf(meanabs, 1e-8f), 2.5f);
    float scale = __fdiv_rn(clipv, 127.f);
    if (lane == 0) g_zscale[row] = scale;
    store_q32((signed char*)g_zq8 + (size_t)row * Dn + lane * 32, yv, scale);
}

// ---------------- launch ----------------
extern "C" void kernel_launch(void* const* d_in, const int* in_sizes, int n_in,
                              void* d_out, int out_size) {
    const float* x         = (const float*)d_in[0];
    const float* mu_r      = (const float*)d_in[1];
    const float* mu_k      = (const float*)d_in[2];
    const float* mu_v      = (const float*)d_in[3];
    const float* mu_g      = (const float*)d_in[4];
    const float* log_decay = (const float*)d_in[5];
    const float* u         = (const float*)d_in[6];
    const float* proj_w    = (const float*)d_in[7];
    const float* ln_g      = (const float*)d_in[8];
    const float* ln_b      = (const float*)d_in[9];
    const float* gn_g      = (const float*)d_in[10];
    const float* gn_b      = (const float*)d_in[11];

    int4 *xq8, *wq8, *zq8;
    float *rkvg, *xscale, *zscale, *wscale;
    cudaGetSymbolAddress((void**)&xq8,    g_xq8);
    cudaGetSymbolAddress((void**)&wq8,    g_wq8);
    cudaGetSymbolAddress((void**)&zq8,    g_zq8);
    cudaGetSymbolAddress((void**)&rkvg,   g_rkvg);
    cudaGetSymbolAddress((void**)&xscale, g_xscale);
    cudaGetSymbolAddress((void**)&zscale, g_zscale);
    cudaGetSymbolAddress((void**)&wscale, g_wscale);

    k_params<<<1, 1024>>>(log_decay, u);
    k_wscale<<<5, 256>>>(proj_w);
    k_wquant<<<5 * Dn * Dn / 256, 256>>>(proj_w);
    k_prep<<<BT / 8, 256>>>(x, mu_r, mu_k, mu_v, mu_g, ln_g, ln_b);

    dim3 ggrid(Dn / 128, BT / 128);
    for (int v = 0; v < 4; v++)
        k_gemm_i8<<<ggrid, 256>>>(xq8 + (size_t)v * (BT * Dn / 16),
                                  wq8 + (size_t)v * (Dn * Dn / 16),
                                  xscale + (size_t)v * BT,
                                  wscale + v,
                                  rkvg + (size_t)v * BT * Dn);

    k_wkv_kv<<<Bn * Hn * NC / 4, 128>>>();
    k_wkv_scan<<<Bn * Hn, 256>>>();
    k_wkv_state<<<Bn * Hn * NC / 4, 128>>>();

    k_gn<<<BT / 8, 256>>>(gn_g, gn_b, ln_g, ln_b);

    k_gemm_i8<<<ggrid, 256>>>(zq8, wq8 + (size_t)4 * (Dn * Dn / 16),
                              zscale, wscale + 4, (float*)d_out);
}